// round 11
// baseline (speedup 1.0000x reference)
#include <cuda_runtime.h>
#include <cuda_fp16.h>
#include <cuda_bf16.h>
#include <stdint.h>

// ---------------- static scratch (no allocation allowed) ----------------
#define N_MAX 100352          // >= N=100000
#define E_MAX 1700000         // >= E=1600000
#define F 128                 // feature dim
#define SA 136                // padded smem row stride (halves)
#define PREP_BLOCKS 128
#define PREP_THREADS 1024

__device__ __align__(16) static __half g_t1[(size_t)N_MAX * F];  // (x@W1)*dis (fp16)
__device__ __align__(16) static __half g_h1[(size_t)N_MAX * F];  // relu layer-1 out (fp16)
__device__ __align__(16) static __half g_t2[(size_t)N_MAX * F];  // (h1@W2)*dis (fp16)
__device__ __align__(16) static __half g_w1t[F * F];             // W1^T fp16 [n][k]
__device__ __align__(16) static __half g_w2t[F * F];             // W2^T fp16 [n][k]
__device__ __align__(16) static float g_dis[N_MAX];
__device__ static int   g_degc[N_MAX];
__device__ static int   g_rowptr[N_MAX + 4];
__device__ static int   g_rank[E_MAX];
__device__ static int   g_csr[E_MAX];
__device__ static int   g_part[PREP_BLOCKS];
__device__ static int   g_counts[1024];
__device__ static int   g_e64;
__device__ static int   g_b64;
__device__ static int   g_bar_cnt[8];
__device__ static int   g_bar_gen[8];

// ---------------- software grid barrier (all blocks co-resident) ----------
__device__ __forceinline__ void gbar(int slot, int nblk) {
    __syncthreads();
    if (threadIdx.x == 0) {
        __threadfence();
        int gen = atomicAdd(&g_bar_gen[slot], 0);
        if (atomicAdd(&g_bar_cnt[slot], 1) == nblk - 1) {
            atomicExch(&g_bar_cnt[slot], 0);
            __threadfence();
            atomicAdd(&g_bar_gen[slot], 1);
        } else {
            while (atomicAdd(&g_bar_gen[slot], 0) == gen) {}
        }
        __threadfence();
    }
    __syncthreads();
}

__device__ __forceinline__ long long load_idx(const void* p, long long i, int is64) {
    if (is64) return ((const long long*)p)[i];
    return (long long)((const int*)p)[i];
}

__device__ __forceinline__ void load_pair(const void* p, long long i, int is64,
                                          int& v0, int& v1) {
    if (is64) {
        longlong2 v = ((const longlong2*)p)[i >> 1];
        v0 = (int)v.x; v1 = (int)v.y;
    } else {
        int2 v = ((const int2*)p)[i >> 1];
        v0 = v.x; v1 = v.y;
    }
}

// ---------------- kernel 1: ALL preprocessing, persistent ----------------
__global__ void __launch_bounds__(PREP_THREADS) prep_kernel(
    const void* __restrict__ edge, const void* __restrict__ batch,
    const float* __restrict__ W1, const float* __restrict__ W2,
    float* __restrict__ out, int outw, int n, int E)
{
    const int T = PREP_BLOCKS * PREP_THREADS;
    int t = threadIdx.x;
    int tid = blockIdx.x * PREP_THREADS + t;

    // ---- phase 0: dtype detect + zero + W transpose/convert ----
    if (blockIdx.x < 2) {
        __shared__ int any;
        if (t == 0) any = 0;
        __syncthreads();
        const int* a = (blockIdx.x == 0) ? (const int*)edge : (const int*)batch;
        int local = 0;
        for (int i = 1 + 2 * t; i < 2048; i += 2 * PREP_THREADS) local |= a[i];
        if (local) atomicOr(&any, 1);
        __syncthreads();
        if (t == 0) {
            int is64 = (any == 0) ? 1 : 0;
            if (blockIdx.x == 0) g_e64 = is64; else g_b64 = is64;
        }
    }
    // W transpose (blocks 2,3): Wt[n][k] = fp16(W[k][n])
    if (blockIdx.x == 2) {
        for (int i = t; i < F * F; i += PREP_THREADS) {
            int k = i >> 7, nn = i & 127;
            g_w1t[nn * F + k] = __float2half(W1[i]);
        }
    }
    if (blockIdx.x == 3) {
        for (int i = t; i < F * F; i += PREP_THREADS) {
            int k = i >> 7, nn = i & 127;
            g_w2t[nn * F + k] = __float2half(W2[i]);
        }
    }
    for (int i = tid; i < n; i += T) g_degc[i] = 0;
    for (int i = tid; i < outw; i += T) out[i] = 0.f;
    for (int i = tid; i < 1024; i += T) g_counts[i] = 0;
    gbar(0, PREP_BLOCKS);

    // ---- phase 1: degree histogram + per-edge rank ----
    {
        int is64 = g_e64;
        int epairs = (E + 1) / 2;
        bool even = ((E & 1) == 0);
        for (int p = tid; p < epairs; p += T) {
            int e0 = 2 * p;
            if (even || e0 + 1 < E) {
                int d0, d1;
                load_pair(edge, (long long)E + e0, is64, d0, d1);
                g_rank[e0]     = atomicAdd(&g_degc[d0], 1);
                g_rank[e0 + 1] = atomicAdd(&g_degc[d1], 1);
            } else {
                int d0 = (int)load_idx(edge, (long long)E + e0, is64);
                g_rank[e0] = atomicAdd(&g_degc[d0], 1);
            }
        }
    }
    gbar(1, PREP_BLOCKS);

    // ---- phase 2: block-local scan + dis ----
    {
        __shared__ int sh[PREP_THREADS];
        int i = tid;
        int v = (i < n) ? g_degc[i] : 0;
        if (i < n) g_dis[i] = rsqrtf((float)(v + 1));   // +1 self loop
        sh[t] = v;
        __syncthreads();
        for (int off = 1; off < PREP_THREADS; off <<= 1) {
            int tmp = (t >= off) ? sh[t - off] : 0;
            __syncthreads();
            sh[t] += tmp;
            __syncthreads();
        }
        if (i < n) g_rowptr[i] = sh[t] - v;
        if (t == PREP_THREADS - 1) g_part[blockIdx.x] = sh[PREP_THREADS - 1];
    }
    gbar(2, PREP_BLOCKS);

    // ---- phase 3: block 0 scans partials ----
    if (blockIdx.x == 0) {
        __shared__ int sp[PREP_BLOCKS];
        int v = (t < PREP_BLOCKS) ? g_part[t] : 0;
        if (t < PREP_BLOCKS) sp[t] = v;
        __syncthreads();
        for (int off = 1; off < PREP_BLOCKS; off <<= 1) {
            int tmp = (t < PREP_BLOCKS && t >= off) ? sp[t - off] : 0;
            __syncthreads();
            if (t < PREP_BLOCKS) sp[t] += tmp;
            __syncthreads();
        }
        if (t < PREP_BLOCKS) g_part[t] = sp[t] - v;
    }
    gbar(3, PREP_BLOCKS);

    // ---- phase 4: add block offsets ----
    {
        int i = tid;
        if (i < n) {
            int r = g_rowptr[i] + g_part[blockIdx.x];
            g_rowptr[i] = r;
            if (i == n - 1) g_rowptr[n] = r + g_degc[i];
        }
    }
    gbar(4, PREP_BLOCKS);

    // ---- phase 5: CSR fill (atomic-free) ----
    {
        int is64 = g_e64;
        int epairs = (E + 1) / 2;
        bool even = ((E & 1) == 0);
        for (int p = tid; p < epairs; p += T) {
            int e0 = 2 * p;
            if (even || e0 + 1 < E) {
                int s0, s1, d0, d1;
                load_pair(edge, (long long)e0, is64, s0, s1);
                load_pair(edge, (long long)E + e0, is64, d0, d1);
                int2 rk = *(const int2*)&g_rank[e0];
                g_csr[g_rowptr[d0] + rk.x] = s0;
                g_csr[g_rowptr[d1] + rk.y] = s1;
            } else {
                int s0 = (int)load_idx(edge, (long long)e0, is64);
                int d0 = (int)load_idx(edge, (long long)E + e0, is64);
                g_csr[g_rowptr[d0] + g_rank[e0]] = s0;
            }
        }
    }
}

// ---------------- tensor-core GEMM: C = fp16((A @ W) * dis[row]) -----------
// 512 threads (16 warps). tile 128x128. warp (wm,wn): rows wm*16..+16, cols wn*64..+64.
template<bool A_IS_HALF>
__global__ void __launch_bounds__(512) gemm_mma_kernel(
    const void* __restrict__ Aptr, const __half* __restrict__ Wt_g,
    __half* __restrict__ C, int n)
{
    extern __shared__ __half sh[];
    __half* As = sh;                 // [128][SA]
    __half* Wt = sh + 128 * SA;      // [128][SA], Wt[n][k]

    int t = threadIdx.x;
    int row0 = blockIdx.x * 128;

    // stage Wt (fp16, coalesced uint4 copy with pad)
    for (int i = t; i < F * F / 8; i += 512) {
        int r = i >> 4, c16 = i & 15;
        *(uint4*)&Wt[r * SA + c16 * 8] = ((const uint4*)Wt_g)[i];
    }

    // stage A tile
    if (A_IS_HALF) {
        const __half* A = (const __half*)Aptr;
        for (int i = t; i < 128 * F / 8; i += 512) {
            int lin = i * 8;
            int r = lin >> 7, c = lin & 127;
            uint4 v = make_uint4(0u, 0u, 0u, 0u);
            if (row0 + r < n) v = *(const uint4*)&A[(size_t)(row0 + r) * F + c];
            *(uint4*)&As[r * SA + c] = v;
        }
    } else {
        const float* A = (const float*)Aptr;
        for (int i = t; i < 128 * F / 4; i += 512) {
            int lin = i * 4;
            int r = lin >> 7, c = lin & 127;
            float4 v = make_float4(0.f, 0.f, 0.f, 0.f);
            if (row0 + r < n) v = *(const float4*)&A[(size_t)(row0 + r) * F + c];
            *(__half2*)&As[r * SA + c]     = __floats2half2_rn(v.x, v.y);
            *(__half2*)&As[r * SA + c + 2] = __floats2half2_rn(v.z, v.w);
        }
    }
    __syncthreads();

    int w = t >> 5, lane = t & 31;
    int wm = w >> 1, wn = w & 1;          // 8 m-tiles x 2 n-halves
    int gq = lane >> 2, tq = lane & 3;
    int m0 = wm * 16;
    int n0 = wn * 64;

    float acc[8][4];
#pragma unroll
    for (int nt = 0; nt < 8; nt++)
#pragma unroll
        for (int c = 0; c < 4; c++) acc[nt][c] = 0.f;

#pragma unroll
    for (int k0 = 0; k0 < F; k0 += 16) {
        uint32_t a0 = *(const uint32_t*)&As[(m0 + gq) * SA + k0 + tq * 2];
        uint32_t a1 = *(const uint32_t*)&As[(m0 + gq + 8) * SA + k0 + tq * 2];
        uint32_t a2 = *(const uint32_t*)&As[(m0 + gq) * SA + k0 + tq * 2 + 8];
        uint32_t a3 = *(const uint32_t*)&As[(m0 + gq + 8) * SA + k0 + tq * 2 + 8];
#pragma unroll
        for (int nt = 0; nt < 8; nt++) {
            uint32_t b0 = *(const uint32_t*)&Wt[(n0 + nt * 8 + gq) * SA + k0 + tq * 2];
            uint32_t b1 = *(const uint32_t*)&Wt[(n0 + nt * 8 + gq) * SA + k0 + tq * 2 + 8];
            asm volatile(
                "mma.sync.aligned.m16n8k16.row.col.f32.f16.f16.f32 "
                "{%0,%1,%2,%3}, {%4,%5,%6,%7}, {%8,%9}, {%0,%1,%2,%3};"
                : "+f"(acc[nt][0]), "+f"(acc[nt][1]), "+f"(acc[nt][2]), "+f"(acc[nt][3])
                : "r"(a0), "r"(a1), "r"(a2), "r"(a3), "r"(b0), "r"(b1));
        }
    }

    int r1 = row0 + m0 + gq;
    int r2 = r1 + 8;
    float d1 = (r1 < n) ? g_dis[r1] : 0.f;
    float d2 = (r2 < n) ? g_dis[r2] : 0.f;
#pragma unroll
    for (int nt = 0; nt < 8; nt++) {
        int col = n0 + nt * 8 + tq * 2;
        if (r1 < n) *(__half2*)&C[(size_t)r1 * F + col] = __floats2half2_rn(acc[nt][0] * d1, acc[nt][1] * d1);
        if (r2 < n) *(__half2*)&C[(size_t)r2 * F + col] = __floats2half2_rn(acc[nt][2] * d2, acc[nt][3] * d2);
    }
}

// ---------------- CSR gather (warp per node, pre-scaled features) ----------
__device__ __forceinline__ void acc2(float4& s, uint2 u) {
    float2 a = __half22float2(*(const __half2*)&u.x);
    float2 b = __half22float2(*(const __half2*)&u.y);
    s.x += a.x; s.y += a.y; s.z += b.x; s.w += b.y;
}

__device__ __forceinline__ float4 agg_row(const uint2* __restrict__ gp,
                                          int node, int lane) {
    uint2 u = __ldg(&gp[(size_t)node * 32 + lane]);   // self loop (pre-scaled)
    float4 s = make_float4(0.f, 0.f, 0.f, 0.f);
    acc2(s, u);
    int i = g_rowptr[node];
    int end = g_rowptr[node + 1];
    for (; i + 8 <= end; i += 8) {
        int s0 = __ldg(&g_csr[i + 0]);
        int s1 = __ldg(&g_csr[i + 1]);
        int s2 = __ldg(&g_csr[i + 2]);
        int s3 = __ldg(&g_csr[i + 3]);
        int s4 = __ldg(&g_csr[i + 4]);
        int s5 = __ldg(&g_csr[i + 5]);
        int s6 = __ldg(&g_csr[i + 6]);
        int s7 = __ldg(&g_csr[i + 7]);
        uint2 u0 = __ldg(&gp[(size_t)s0 * 32 + lane]);
        uint2 u1 = __ldg(&gp[(size_t)s1 * 32 + lane]);
        uint2 u2 = __ldg(&gp[(size_t)s2 * 32 + lane]);
        uint2 u3 = __ldg(&gp[(size_t)s3 * 32 + lane]);
        uint2 u4 = __ldg(&gp[(size_t)s4 * 32 + lane]);
        uint2 u5 = __ldg(&gp[(size_t)s5 * 32 + lane]);
        uint2 u6 = __ldg(&gp[(size_t)s6 * 32 + lane]);
        uint2 u7 = __ldg(&gp[(size_t)s7 * 32 + lane]);
        acc2(s, u0); acc2(s, u1); acc2(s, u2); acc2(s, u3);
        acc2(s, u4); acc2(s, u5); acc2(s, u6); acc2(s, u7);
    }
    if (i + 4 <= end) {
        int s0 = __ldg(&g_csr[i + 0]);
        int s1 = __ldg(&g_csr[i + 1]);
        int s2 = __ldg(&g_csr[i + 2]);
        int s3 = __ldg(&g_csr[i + 3]);
        uint2 u0 = __ldg(&gp[(size_t)s0 * 32 + lane]);
        uint2 u1 = __ldg(&gp[(size_t)s1 * 32 + lane]);
        uint2 u2 = __ldg(&gp[(size_t)s2 * 32 + lane]);
        uint2 u3 = __ldg(&gp[(size_t)s3 * 32 + lane]);
        acc2(s, u0); acc2(s, u1); acc2(s, u2); acc2(s, u3);
        i += 4;
    }
    for (; i < end; i++) {
        int s0 = __ldg(&g_csr[i]);
        uint2 u0 = __ldg(&gp[(size_t)s0 * 32 + lane]);
        acc2(s, u0);
    }
    return s;
}

__global__ void __launch_bounds__(256) agg1_kernel(const float* __restrict__ b, int n) {
    int w = (blockIdx.x * blockDim.x + threadIdx.x) >> 5;
    int lane = threadIdx.x & 31;
    if (w >= n) return;
    float4 s = agg_row((const uint2*)g_t1, w, lane);
    float d = g_dis[w];
    float4 bb = __ldg((const float4*)&b[lane * 4]);
    float ox = fmaxf(fmaf(d, s.x, bb.x), 0.f);
    float oy = fmaxf(fmaf(d, s.y, bb.y), 0.f);
    float oz = fmaxf(fmaf(d, s.z, bb.z), 0.f);
    float ow = fmaxf(fmaf(d, s.w, bb.w), 0.f);
    __half2 p0 = __floats2half2_rn(ox, oy);
    __half2 p1 = __floats2half2_rn(oz, ow);
    uint2 st;
    st.x = *(uint32_t*)&p0;
    st.y = *(uint32_t*)&p1;
    ((uint2*)g_h1)[(size_t)w * 32 + lane] = st;
}

__global__ void __launch_bounds__(256) agg2_kernel(
    const void* __restrict__ batch, const float* __restrict__ b,
    float* __restrict__ out, int n)
{
    int w = (blockIdx.x * blockDim.x + threadIdx.x) >> 5;
    int lane = threadIdx.x & 31;
    if (w >= n) return;
    float4 s = agg_row((const uint2*)g_t2, w, lane);
    float d = g_dis[w];
    float4 bb = __ldg((const float4*)&b[lane * 4]);
    float4 o;
    o.x = fmaxf(fmaf(d, s.x, bb.x), 0.f);
    o.y = fmaxf(fmaf(d, s.y, bb.y), 0.f);
    o.z = fmaxf(fmaf(d, s.z, bb.z), 0.f);
    o.w = fmaxf(fmaf(d, s.w, bb.w), 0.f);
    long long gid = load_idx(batch, w, g_b64);
    float* p = &out[(size_t)gid * F + lane * 4];
    asm volatile("red.global.add.v4.f32 [%0], {%1,%2,%3,%4};"
                 :: "l"(p), "f"(o.x), "f"(o.y), "f"(o.z), "f"(o.w) : "memory");
    if (lane == 0) atomicAdd(&g_counts[gid], 1);
}

__global__ void div_kernel(float* __restrict__ out, int gtot) {
    int i = blockIdx.x * blockDim.x + threadIdx.x;
    if (i >= gtot * F) return;
    int gidx = i >> 7;
    float cnt = (float)max(g_counts[gidx], 1);
    out[i] = out[i] / cnt;
}

// ---------------- launch ----------------
extern "C" void kernel_launch(void* const* d_in, const int* in_sizes, int n_in,
                              void* d_out, int out_size) {
    const float* x    = (const float*)d_in[0];
    const void*  edge = d_in[1];
    const void*  batch= d_in[2];
    const float* W1   = (const float*)d_in[3];
    const float* b1   = (const float*)d_in[4];
    const float* W2   = (const float*)d_in[5];
    const float* b2   = (const float*)d_in[6];
    float* out = (float*)d_out;

    int N = in_sizes[0] / F;
    int E = in_sizes[1] / 2;
    int G = out_size / F;

    void *p_t1, *p_h1, *p_t2, *p_w1t, *p_w2t;
    cudaGetSymbolAddress(&p_t1, g_t1);
    cudaGetSymbolAddress(&p_h1, g_h1);
    cudaGetSymbolAddress(&p_t2, g_t2);
    cudaGetSymbolAddress(&p_w1t, g_w1t);
    cudaGetSymbolAddress(&p_w2t, g_w2t);

    const int SMEM = 2 * 128 * SA * (int)sizeof(__half);   // 69632 bytes
    cudaFuncSetAttribute(gemm_mma_kernel<false>, cudaFuncAttributeMaxDynamicSharedMemorySize, SMEM);
    cudaFuncSetAttribute(gemm_mma_kernel<true>,  cudaFuncAttributeMaxDynamicSharedMemorySize, SMEM);

    const int TB = 256;
    int gemm_grid = (N + 127) / 128;
    int agg_grid = (N + 7) / 8;

    prep_kernel<<<PREP_BLOCKS, PREP_THREADS>>>(edge, batch, W1, W2, out, G * F, N, E);
    gemm_mma_kernel<false><<<gemm_grid, 512, SMEM>>>(x, (const __half*)p_w1t, (__half*)p_t1, N);
    agg1_kernel<<<agg_grid, TB>>>(b1, N);
    gemm_mma_kernel<true><<<gemm_grid, 512, SMEM>>>(p_h1, (const __half*)p_w2t, (__half*)p_t2, N);
    agg2_kernel<<<agg_grid, TB>>>(batch, b2, out, N);
    div_kernel<<<(G * F + TB - 1) / TB, TB>>>(out, G);
}

// round 12
// speedup vs baseline: 1.0374x; 1.0374x over previous
#include <cuda_runtime.h>
#include <cuda_fp16.h>
#include <cuda_bf16.h>
#include <stdint.h>

// ---------------- static scratch (no allocation allowed) ----------------
#define N_MAX 100352          // >= N=100000
#define E_MAX 1700000         // >= E=1600000
#define F 128                 // feature dim
#define SA 136                // padded smem row stride (halves)
#define PREP_BLOCKS 128
#define PREP_THREADS 1024

__device__ __align__(16) static __half g_t1[(size_t)N_MAX * F];  // (x@W1)*dis (fp16)
__device__ __align__(16) static __half g_h1[(size_t)N_MAX * F];  // relu layer-1 out (fp16)
__device__ __align__(16) static __half g_t2[(size_t)N_MAX * F];  // (h1@W2)*dis (fp16)
__device__ __align__(16) static __half g_w1t[F * F];             // W1^T fp16 [n][k]
__device__ __align__(16) static __half g_w2t[F * F];             // W2^T fp16 [n][k]
__device__ __align__(16) static float g_dis[N_MAX];
__device__ static int   g_degc[N_MAX];
__device__ static int   g_rowptr[N_MAX + 4];
__device__ static int   g_rank[E_MAX];
__device__ __align__(16) static int g_csr[E_MAX];
__device__ static int   g_part[PREP_BLOCKS];
__device__ static int   g_gstart[1024];
__device__ static int   g_gend[1024];
__device__ static float g_inv[1024];
__device__ static int   g_e64;
__device__ static int   g_b64;
__device__ static int   g_bar_cnt[8];
__device__ static int   g_bar_gen[8];

// ---------------- software grid barrier (all blocks co-resident) ----------
__device__ __forceinline__ void gbar(int slot, int nblk) {
    __syncthreads();
    if (threadIdx.x == 0) {
        __threadfence();
        int gen = atomicAdd(&g_bar_gen[slot], 0);
        if (atomicAdd(&g_bar_cnt[slot], 1) == nblk - 1) {
            atomicExch(&g_bar_cnt[slot], 0);
            __threadfence();
            atomicAdd(&g_bar_gen[slot], 1);
        } else {
            while (atomicAdd(&g_bar_gen[slot], 0) == gen) {}
        }
        __threadfence();
    }
    __syncthreads();
}

__device__ __forceinline__ long long load_idx(const void* p, long long i, int is64) {
    if (is64) return ((const long long*)p)[i];
    return (long long)((const int*)p)[i];
}

__device__ __forceinline__ void load_pair(const void* p, long long i, int is64,
                                          int& v0, int& v1) {
    if (is64) {
        longlong2 v = ((const longlong2*)p)[i >> 1];
        v0 = (int)v.x; v1 = (int)v.y;
    } else {
        int2 v = ((const int2*)p)[i >> 1];
        v0 = v.x; v1 = v.y;
    }
}

// ---------------- kernel 1: detect + zero + Wt + deg/rank + graph bounds ---
__global__ void __launch_bounds__(PREP_THREADS) prep1_kernel(
    const void* __restrict__ edge, const void* __restrict__ batch,
    const float* __restrict__ W1, const float* __restrict__ W2,
    float* __restrict__ out, int outw, int n, int E)
{
    const int T = PREP_BLOCKS * PREP_THREADS;
    int t = threadIdx.x;
    int tid = blockIdx.x * PREP_THREADS + t;

    // ---- phase 0: dtype detect + W transpose + zero ----
    if (blockIdx.x < 2) {
        __shared__ int any;
        if (t == 0) any = 0;
        __syncthreads();
        const int* a = (blockIdx.x == 0) ? (const int*)edge : (const int*)batch;
        int local = 0;
        for (int i = 1 + 2 * t; i < 2048; i += 2 * PREP_THREADS) local |= a[i];
        if (local) atomicOr(&any, 1);
        __syncthreads();
        if (t == 0) {
            int is64 = (any == 0) ? 1 : 0;
            if (blockIdx.x == 0) g_e64 = is64; else g_b64 = is64;
        }
    }
    if (blockIdx.x == 2) {
        for (int i = t; i < F * F; i += PREP_THREADS) {
            int k = i >> 7, nn = i & 127;
            g_w1t[nn * F + k] = __float2half(W1[i]);
        }
    }
    if (blockIdx.x == 3) {
        for (int i = t; i < F * F; i += PREP_THREADS) {
            int k = i >> 7, nn = i & 127;
            g_w2t[nn * F + k] = __float2half(W2[i]);
        }
    }
    for (int i = tid; i < n; i += T) g_degc[i] = 0;
    for (int i = tid; i < outw; i += T) out[i] = 0.f;
    for (int i = tid; i < 1024; i += T) { g_gstart[i] = 0; g_gend[i] = 0; }
    gbar(0, PREP_BLOCKS);

    // ---- phase 1: degree histogram + per-edge rank ----
    {
        int is64 = g_e64;
        int epairs = (E + 1) / 2;
        bool even = ((E & 1) == 0);
        for (int p = tid; p < epairs; p += T) {
            int e0 = 2 * p;
            if (even || e0 + 1 < E) {
                int d0, d1;
                load_pair(edge, (long long)E + e0, is64, d0, d1);
                g_rank[e0]     = atomicAdd(&g_degc[d0], 1);
                g_rank[e0 + 1] = atomicAdd(&g_degc[d1], 1);
            } else {
                int d0 = (int)load_idx(edge, (long long)E + e0, is64);
                g_rank[e0] = atomicAdd(&g_degc[d0], 1);
            }
        }
    }
    // ---- graph boundary detection on sorted batch (atomic-free) ----
    {
        int is64b = g_b64;
        for (int i = tid; i < n; i += T) {
            int b = (int)load_idx(batch, i, is64b);
            int prev = (i > 0) ? (int)load_idx(batch, (long long)i - 1, is64b) : -1;
            int next = (i + 1 < n) ? (int)load_idx(batch, (long long)i + 1, is64b) : -2;
            if (b != prev) g_gstart[b] = i;
            if (b != next) g_gend[b] = i + 1;
        }
    }
}

// ---------------- kernel 2: scan(+dis) + inv-counts + CSR fill -------------
__global__ void __launch_bounds__(PREP_THREADS) prep2_kernel(
    const void* __restrict__ edge, int n, int E)
{
    const int T = PREP_BLOCKS * PREP_THREADS;
    int t = threadIdx.x;
    int tid = blockIdx.x * PREP_THREADS + t;

    // inv-counts (needs prep1's gstart/gend; kernel boundary guarantees it)
    if (blockIdx.x == PREP_BLOCKS - 1 && t < 1024) {
        int c = g_gend[t] - g_gstart[t];
        g_inv[t] = 1.f / (float)max(c, 1);
    }

    // ---- block-local scan + dis ----
    {
        __shared__ int sh[PREP_THREADS];
        int i = tid;
        int v = (i < n) ? g_degc[i] : 0;
        if (i < n) g_dis[i] = rsqrtf((float)(v + 1));   // +1 self loop
        sh[t] = v;
        __syncthreads();
        for (int off = 1; off < PREP_THREADS; off <<= 1) {
            int tmp = (t >= off) ? sh[t - off] : 0;
            __syncthreads();
            sh[t] += tmp;
            __syncthreads();
        }
        if (i < n) g_rowptr[i] = sh[t] - v;
        if (t == PREP_THREADS - 1) g_part[blockIdx.x] = sh[PREP_THREADS - 1];
    }
    gbar(1, PREP_BLOCKS);

    // ---- block 0 scans partials ----
    if (blockIdx.x == 0) {
        __shared__ int sp[PREP_BLOCKS];
        int v = (t < PREP_BLOCKS) ? g_part[t] : 0;
        if (t < PREP_BLOCKS) sp[t] = v;
        __syncthreads();
        for (int off = 1; off < PREP_BLOCKS; off <<= 1) {
            int tmp = (t < PREP_BLOCKS && t >= off) ? sp[t - off] : 0;
            __syncthreads();
            if (t < PREP_BLOCKS) sp[t] += tmp;
            __syncthreads();
        }
        if (t < PREP_BLOCKS) g_part[t] = sp[t] - v;
    }
    gbar(2, PREP_BLOCKS);

    // ---- add block offsets ----
    {
        int i = tid;
        if (i < n) {
            int r = g_rowptr[i] + g_part[blockIdx.x];
            g_rowptr[i] = r;
            if (i == n - 1) g_rowptr[n] = r + g_degc[i];
        }
    }
    gbar(3, PREP_BLOCKS);

    // ---- CSR fill (atomic-free) ----
    {
        int is64 = g_e64;
        int epairs = (E + 1) / 2;
        bool even = ((E & 1) == 0);
        for (int p = tid; p < epairs; p += T) {
            int e0 = 2 * p;
            if (even || e0 + 1 < E) {
                int s0, s1, d0, d1;
                load_pair(edge, (long long)e0, is64, s0, s1);
                load_pair(edge, (long long)E + e0, is64, d0, d1);
                int2 rk = *(const int2*)&g_rank[e0];
                g_csr[g_rowptr[d0] + rk.x] = s0;
                g_csr[g_rowptr[d1] + rk.y] = s1;
            } else {
                int s0 = (int)load_idx(edge, (long long)e0, is64);
                int d0 = (int)load_idx(edge, (long long)E + e0, is64);
                g_csr[g_rowptr[d0] + g_rank[e0]] = s0;
            }
        }
    }
}

// ---------------- tensor-core GEMM: C = fp16((A @ W) * dis[row]) -----------
template<bool A_IS_HALF>
__global__ void __launch_bounds__(512) gemm_mma_kernel(
    const void* __restrict__ Aptr, const __half* __restrict__ Wt_g,
    __half* __restrict__ C, int n)
{
    extern __shared__ __half sh[];
    __half* As = sh;                 // [128][SA]
    __half* Wt = sh + 128 * SA;      // [128][SA], Wt[n][k]

    int t = threadIdx.x;
    int row0 = blockIdx.x * 128;

    for (int i = t; i < F * F / 8; i += 512) {
        int r = i >> 4, c16 = i & 15;
        *(uint4*)&Wt[r * SA + c16 * 8] = ((const uint4*)Wt_g)[i];
    }

    if (A_IS_HALF) {
        const __half* A = (const __half*)Aptr;
        for (int i = t; i < 128 * F / 8; i += 512) {
            int lin = i * 8;
            int r = lin >> 7, c = lin & 127;
            uint4 v = make_uint4(0u, 0u, 0u, 0u);
            if (row0 + r < n) v = *(const uint4*)&A[(size_t)(row0 + r) * F + c];
            *(uint4*)&As[r * SA + c] = v;
        }
    } else {
        const float* A = (const float*)Aptr;
        for (int i = t; i < 128 * F / 4; i += 512) {
            int lin = i * 4;
            int r = lin >> 7, c = lin & 127;
            float4 v = make_float4(0.f, 0.f, 0.f, 0.f);
            if (row0 + r < n) v = *(const float4*)&A[(size_t)(row0 + r) * F + c];
            *(__half2*)&As[r * SA + c]     = __floats2half2_rn(v.x, v.y);
            *(__half2*)&As[r * SA + c + 2] = __floats2half2_rn(v.z, v.w);
        }
    }
    __syncthreads();

    int w = t >> 5, lane = t & 31;
    int wm = w >> 1, wn = w & 1;
    int gq = lane >> 2, tq = lane & 3;
    int m0 = wm * 16;
    int n0 = wn * 64;

    float acc[8][4];
#pragma unroll
    for (int nt = 0; nt < 8; nt++)
#pragma unroll
        for (int c = 0; c < 4; c++) acc[nt][c] = 0.f;

#pragma unroll
    for (int k0 = 0; k0 < F; k0 += 16) {
        uint32_t a0 = *(const uint32_t*)&As[(m0 + gq) * SA + k0 + tq * 2];
        uint32_t a1 = *(const uint32_t*)&As[(m0 + gq + 8) * SA + k0 + tq * 2];
        uint32_t a2 = *(const uint32_t*)&As[(m0 + gq) * SA + k0 + tq * 2 + 8];
        uint32_t a3 = *(const uint32_t*)&As[(m0 + gq + 8) * SA + k0 + tq * 2 + 8];
#pragma unroll
        for (int nt = 0; nt < 8; nt++) {
            uint32_t b0 = *(const uint32_t*)&Wt[(n0 + nt * 8 + gq) * SA + k0 + tq * 2];
            uint32_t b1 = *(const uint32_t*)&Wt[(n0 + nt * 8 + gq) * SA + k0 + tq * 2 + 8];
            asm volatile(
                "mma.sync.aligned.m16n8k16.row.col.f32.f16.f16.f32 "
                "{%0,%1,%2,%3}, {%4,%5,%6,%7}, {%8,%9}, {%0,%1,%2,%3};"
                : "+f"(acc[nt][0]), "+f"(acc[nt][1]), "+f"(acc[nt][2]), "+f"(acc[nt][3])
                : "r"(a0), "r"(a1), "r"(a2), "r"(a3), "r"(b0), "r"(b1));
        }
    }

    int r1 = row0 + m0 + gq;
    int r2 = r1 + 8;
    float d1 = (r1 < n) ? g_dis[r1] : 0.f;
    float d2 = (r2 < n) ? g_dis[r2] : 0.f;
#pragma unroll
    for (int nt = 0; nt < 8; nt++) {
        int col = n0 + nt * 8 + tq * 2;
        if (r1 < n) *(__half2*)&C[(size_t)r1 * F + col] = __floats2half2_rn(acc[nt][0] * d1, acc[nt][1] * d1);
        if (r2 < n) *(__half2*)&C[(size_t)r2 * F + col] = __floats2half2_rn(acc[nt][2] * d2, acc[nt][3] * d2);
    }
}

// ---------------- CSR gather (warp/node, vectorized index loads) -----------
__device__ __forceinline__ void acc2(float4& s, uint2 u) {
    float2 a = __half22float2(*(const __half2*)&u.x);
    float2 b = __half22float2(*(const __half2*)&u.y);
    s.x += a.x; s.y += a.y; s.z += b.x; s.w += b.y;
}

__device__ __forceinline__ float4 agg_row(const uint2* __restrict__ gp,
                                          int node, int lane) {
    float4 s = make_float4(0.f, 0.f, 0.f, 0.f);
    acc2(s, __ldg(&gp[(size_t)node * 32 + lane]));    // self loop (pre-scaled)
    int i = g_rowptr[node];
    int end = g_rowptr[node + 1];
    // peel to 16B alignment of g_csr index loads
    while (i < end && (i & 3)) {
        acc2(s, __ldg(&gp[(size_t)__ldg(&g_csr[i]) * 32 + lane]));
        i++;
    }
    for (; i + 8 <= end; i += 8) {
        int4 ia = __ldg((const int4*)&g_csr[i]);
        int4 ib = __ldg((const int4*)&g_csr[i + 4]);
        uint2 u0 = __ldg(&gp[(size_t)ia.x * 32 + lane]);
        uint2 u1 = __ldg(&gp[(size_t)ia.y * 32 + lane]);
        uint2 u2 = __ldg(&gp[(size_t)ia.z * 32 + lane]);
        uint2 u3 = __ldg(&gp[(size_t)ia.w * 32 + lane]);
        uint2 u4 = __ldg(&gp[(size_t)ib.x * 32 + lane]);
        uint2 u5 = __ldg(&gp[(size_t)ib.y * 32 + lane]);
        uint2 u6 = __ldg(&gp[(size_t)ib.z * 32 + lane]);
        uint2 u7 = __ldg(&gp[(size_t)ib.w * 32 + lane]);
        acc2(s, u0); acc2(s, u1); acc2(s, u2); acc2(s, u3);
        acc2(s, u4); acc2(s, u5); acc2(s, u6); acc2(s, u7);
    }
    if (i + 4 <= end) {
        int4 ia = __ldg((const int4*)&g_csr[i]);
        uint2 u0 = __ldg(&gp[(size_t)ia.x * 32 + lane]);
        uint2 u1 = __ldg(&gp[(size_t)ia.y * 32 + lane]);
        uint2 u2 = __ldg(&gp[(size_t)ia.z * 32 + lane]);
        uint2 u3 = __ldg(&gp[(size_t)ia.w * 32 + lane]);
        acc2(s, u0); acc2(s, u1); acc2(s, u2); acc2(s, u3);
        i += 4;
    }
    for (; i < end; i++) {
        acc2(s, __ldg(&gp[(size_t)__ldg(&g_csr[i]) * 32 + lane]));
    }
    return s;
}

// kernel 4: h1 = fp16(relu(dis*sum + b))
__global__ void __launch_bounds__(256) agg1_kernel(const float* __restrict__ b, int n) {
    int w = (blockIdx.x * blockDim.x + threadIdx.x) >> 5;
    int lane = threadIdx.x & 31;
    if (w >= n) return;
    float4 s = agg_row((const uint2*)g_t1, w, lane);
    float d = g_dis[w];
    float4 bb = __ldg((const float4*)&b[lane * 4]);
    float ox = fmaxf(fmaf(d, s.x, bb.x), 0.f);
    float oy = fmaxf(fmaf(d, s.y, bb.y), 0.f);
    float oz = fmaxf(fmaf(d, s.z, bb.z), 0.f);
    float ow = fmaxf(fmaf(d, s.w, bb.w), 0.f);
    __half2 p0 = __floats2half2_rn(ox, oy);
    __half2 p1 = __floats2half2_rn(oz, ow);
    uint2 st;
    st.x = *(uint32_t*)&p0;
    st.y = *(uint32_t*)&p1;
    ((uint2*)g_h1)[(size_t)w * 32 + lane] = st;
}

// kernel 6: o = relu(dis*sum + b) * inv_count; mean-pool scatter (no div pass)
__global__ void __launch_bounds__(256) agg2_kernel(
    const void* __restrict__ batch, const float* __restrict__ b,
    float* __restrict__ out, int n)
{
    int w = (blockIdx.x * blockDim.x + threadIdx.x) >> 5;
    int lane = threadIdx.x & 31;
    if (w >= n) return;
    float4 s = agg_row((const uint2*)g_t2, w, lane);
    float d = g_dis[w];
    float4 bb = __ldg((const float4*)&b[lane * 4]);
    long long gid = load_idx(batch, w, g_b64);
    float inv = __ldg(&g_inv[gid]);
    float ox = fmaxf(fmaf(d, s.x, bb.x), 0.f) * inv;
    float oy = fmaxf(fmaf(d, s.y, bb.y), 0.f) * inv;
    float oz = fmaxf(fmaf(d, s.z, bb.z), 0.f) * inv;
    float ow = fmaxf(fmaf(d, s.w, bb.w), 0.f) * inv;
    float* p = &out[(size_t)gid * F + lane * 4];
    asm volatile("red.global.add.v4.f32 [%0], {%1,%2,%3,%4};"
                 :: "l"(p), "f"(ox), "f"(oy), "f"(oz), "f"(ow) : "memory");
}

// ---------------- launch ----------------
extern "C" void kernel_launch(void* const* d_in, const int* in_sizes, int n_in,
                              void* d_out, int out_size) {
    const float* x    = (const float*)d_in[0];
    const void*  edge = d_in[1];
    const void*  batch= d_in[2];
    const float* W1   = (const float*)d_in[3];
    const float* b1   = (const float*)d_in[4];
    const float* W2   = (const float*)d_in[5];
    const float* b2   = (const float*)d_in[6];
    float* out = (float*)d_out;

    int N = in_sizes[0] / F;
    int E = in_sizes[1] / 2;
    int G = out_size / F;

    void *p_t1, *p_h1, *p_t2, *p_w1t, *p_w2t;
    cudaGetSymbolAddress(&p_t1, g_t1);
    cudaGetSymbolAddress(&p_h1, g_h1);
    cudaGetSymbolAddress(&p_t2, g_t2);
    cudaGetSymbolAddress(&p_w1t, g_w1t);
    cudaGetSymbolAddress(&p_w2t, g_w2t);

    const int SMEM = 2 * 128 * SA * (int)sizeof(__half);   // 69632 bytes
    cudaFuncSetAttribute(gemm_mma_kernel<false>, cudaFuncAttributeMaxDynamicSharedMemorySize, SMEM);
    cudaFuncSetAttribute(gemm_mma_kernel<true>,  cudaFuncAttributeMaxDynamicSharedMemorySize, SMEM);

    const int TB = 256;
    int gemm_grid = (N + 127) / 128;
    int agg_grid = (N + 7) / 8;

    // launches: 0 prep1, 1 prep2, 2 gemm1, 3 agg1 (profiled), 4 gemm2, 5 agg2
    prep1_kernel<<<PREP_BLOCKS, PREP_THREADS>>>(edge, batch, W1, W2, out, G * F, N, E);
    prep2_kernel<<<PREP_BLOCKS, PREP_THREADS>>>(edge, N, E);
    gemm_mma_kernel<false><<<gemm_grid, 512, SMEM>>>(x, (const __half*)p_w1t, (__half*)p_t1, N);
    agg1_kernel<<<agg_grid, TB>>>(b1, N);
    gemm_mma_kernel<true><<<gemm_grid, 512, SMEM>>>(p_h1, (const __half*)p_w2t, (__half*)p_t2, N);
    agg2_kernel<<<agg_grid, TB>>>(batch, b2, out, N);
}

// round 13
// speedup vs baseline: 1.0888x; 1.0496x over previous
#include <cuda_runtime.h>
#include <cuda_fp16.h>
#include <cuda_bf16.h>
#include <stdint.h>

// ---------------- static scratch (no allocation allowed) ----------------
#define N_MAX 100352          // >= N=100000
#define E_MAX 1700000         // >= E=1600000
#define F 128                 // feature dim
#define SA 136                // padded smem row stride (halves)
#define PREP_BLOCKS 128
#define PREP_THREADS 1024

__device__ __align__(16) static __half g_t1[(size_t)N_MAX * F];  // (x@W1)*dis (fp16)
__device__ __align__(16) static __half g_h1[(size_t)N_MAX * F];  // relu layer-1 out (fp16)
__device__ __align__(16) static __half g_t2[(size_t)N_MAX * F];  // (h1@W2)*dis (fp16)
__device__ __align__(16) static __half g_w1t[F * F];             // W1^T fp16 [n][k]
__device__ __align__(16) static __half g_w2t[F * F];             // W2^T fp16 [n][k]
__device__ __align__(16) static float g_dis[N_MAX];
__device__ static int   g_degc[N_MAX];
__device__ static int   g_rowptr[N_MAX + 4];
__device__ static int   g_rank[E_MAX];
__device__ __align__(16) static int g_csr[E_MAX];
__device__ static int   g_part[PREP_BLOCKS];
__device__ static int   g_gstart[1024];
__device__ static int   g_gend[1024];
__device__ static float g_inv[1024];
__device__ static int   g_e64;
__device__ static int   g_b64;
__device__ static int   g_bar_cnt[8];
__device__ static int   g_bar_gen[8];

// ---------------- software grid barrier (all blocks co-resident) ----------
__device__ __forceinline__ void gbar(int slot, int nblk) {
    __syncthreads();
    if (threadIdx.x == 0) {
        __threadfence();
        int gen = atomicAdd(&g_bar_gen[slot], 0);
        if (atomicAdd(&g_bar_cnt[slot], 1) == nblk - 1) {
            atomicExch(&g_bar_cnt[slot], 0);
            __threadfence();
            atomicAdd(&g_bar_gen[slot], 1);
        } else {
            while (atomicAdd(&g_bar_gen[slot], 0) == gen) {}
        }
        __threadfence();
    }
    __syncthreads();
}

__device__ __forceinline__ long long load_idx(const void* p, long long i, int is64) {
    if (is64) return ((const long long*)p)[i];
    return (long long)((const int*)p)[i];
}

__device__ __forceinline__ void load_pair(const void* p, long long i, int is64,
                                          int& v0, int& v1) {
    if (is64) {
        longlong2 v = ((const longlong2*)p)[i >> 1];
        v0 = (int)v.x; v1 = (int)v.y;
    } else {
        int2 v = ((const int2*)p)[i >> 1];
        v0 = v.x; v1 = v.y;
    }
}

// ---------------- kernel 1: detect + zero + Wt + deg/rank + graph bounds ---
__global__ void __launch_bounds__(PREP_THREADS) prep1_kernel(
    const void* __restrict__ edge, const void* __restrict__ batch,
    const float* __restrict__ W1, const float* __restrict__ W2,
    float* __restrict__ out, int outw, int n, int E)
{
    const int T = PREP_BLOCKS * PREP_THREADS;
    int t = threadIdx.x;
    int tid = blockIdx.x * PREP_THREADS + t;

    if (blockIdx.x < 2) {
        __shared__ int any;
        if (t == 0) any = 0;
        __syncthreads();
        const int* a = (blockIdx.x == 0) ? (const int*)edge : (const int*)batch;
        int local = 0;
        for (int i = 1 + 2 * t; i < 2048; i += 2 * PREP_THREADS) local |= a[i];
        if (local) atomicOr(&any, 1);
        __syncthreads();
        if (t == 0) {
            int is64 = (any == 0) ? 1 : 0;
            if (blockIdx.x == 0) g_e64 = is64; else g_b64 = is64;
        }
    }
    if (blockIdx.x == 2) {
        for (int i = t; i < F * F; i += PREP_THREADS) {
            int k = i >> 7, nn = i & 127;
            g_w1t[nn * F + k] = __float2half(W1[i]);
        }
    }
    if (blockIdx.x == 3) {
        for (int i = t; i < F * F; i += PREP_THREADS) {
            int k = i >> 7, nn = i & 127;
            g_w2t[nn * F + k] = __float2half(W2[i]);
        }
    }
    for (int i = tid; i < n; i += T) g_degc[i] = 0;
    for (int i = tid; i < outw; i += T) out[i] = 0.f;
    for (int i = tid; i < 1024; i += T) { g_gstart[i] = 0; g_gend[i] = 0; }
    gbar(0, PREP_BLOCKS);

    // ---- degree histogram + per-edge rank ----
    {
        int is64 = g_e64;
        int epairs = (E + 1) / 2;
        bool even = ((E & 1) == 0);
        for (int p = tid; p < epairs; p += T) {
            int e0 = 2 * p;
            if (even || e0 + 1 < E) {
                int d0, d1;
                load_pair(edge, (long long)E + e0, is64, d0, d1);
                g_rank[e0]     = atomicAdd(&g_degc[d0], 1);
                g_rank[e0 + 1] = atomicAdd(&g_degc[d1], 1);
            } else {
                int d0 = (int)load_idx(edge, (long long)E + e0, is64);
                g_rank[e0] = atomicAdd(&g_degc[d0], 1);
            }
        }
    }
    // ---- graph boundary detection on sorted batch ----
    {
        int is64b = g_b64;
        for (int i = tid; i < n; i += T) {
            int b = (int)load_idx(batch, i, is64b);
            int prev = (i > 0) ? (int)load_idx(batch, (long long)i - 1, is64b) : -1;
            int next = (i + 1 < n) ? (int)load_idx(batch, (long long)i + 1, is64b) : -2;
            if (b != prev) g_gstart[b] = i;
            if (b != next) g_gend[b] = i + 1;
        }
    }
}

// ---------------- kernel 2: scan(+dis) + inv-counts + CSR fill -------------
__global__ void __launch_bounds__(PREP_THREADS) prep2_kernel(
    const void* __restrict__ edge, int n, int E)
{
    const int T = PREP_BLOCKS * PREP_THREADS;
    int t = threadIdx.x;
    int tid = blockIdx.x * PREP_THREADS + t;

    if (blockIdx.x == PREP_BLOCKS - 1 && t < 1024) {
        int c = g_gend[t] - g_gstart[t];
        g_inv[t] = 1.f / (float)max(c, 1);
    }

    {
        __shared__ int sh[PREP_THREADS];
        int i = tid;
        int v = (i < n) ? g_degc[i] : 0;
        if (i < n) g_dis[i] = rsqrtf((float)(v + 1));   // +1 self loop
        sh[t] = v;
        __syncthreads();
        for (int off = 1; off < PREP_THREADS; off <<= 1) {
            int tmp = (t >= off) ? sh[t - off] : 0;
            __syncthreads();
            sh[t] += tmp;
            __syncthreads();
        }
        if (i < n) g_rowptr[i] = sh[t] - v;
        if (t == PREP_THREADS - 1) g_part[blockIdx.x] = sh[PREP_THREADS - 1];
    }
    gbar(1, PREP_BLOCKS);

    if (blockIdx.x == 0) {
        __shared__ int sp[PREP_BLOCKS];
        int v = (t < PREP_BLOCKS) ? g_part[t] : 0;
        if (t < PREP_BLOCKS) sp[t] = v;
        __syncthreads();
        for (int off = 1; off < PREP_BLOCKS; off <<= 1) {
            int tmp = (t < PREP_BLOCKS && t >= off) ? sp[t - off] : 0;
            __syncthreads();
            if (t < PREP_BLOCKS) sp[t] += tmp;
            __syncthreads();
        }
        if (t < PREP_BLOCKS) g_part[t] = sp[t] - v;
    }
    gbar(2, PREP_BLOCKS);

    {
        int i = tid;
        if (i < n) {
            int r = g_rowptr[i] + g_part[blockIdx.x];
            g_rowptr[i] = r;
            if (i == n - 1) g_rowptr[n] = r + g_degc[i];
        }
    }
    gbar(3, PREP_BLOCKS);

    {
        int is64 = g_e64;
        int epairs = (E + 1) / 2;
        bool even = ((E & 1) == 0);
        for (int p = tid; p < epairs; p += T) {
            int e0 = 2 * p;
            if (even || e0 + 1 < E) {
                int s0, s1, d0, d1;
                load_pair(edge, (long long)e0, is64, s0, s1);
                load_pair(edge, (long long)E + e0, is64, d0, d1);
                int2 rk = *(const int2*)&g_rank[e0];
                g_csr[g_rowptr[d0] + rk.x] = s0;
                g_csr[g_rowptr[d1] + rk.y] = s1;
            } else {
                int s0 = (int)load_idx(edge, (long long)e0, is64);
                int d0 = (int)load_idx(edge, (long long)E + e0, is64);
                g_csr[g_rowptr[d0] + g_rank[e0]] = s0;
            }
        }
    }
}

// ---------------- tensor-core GEMM: C = fp16((A @ W) * dis[row]) -----------
template<bool A_IS_HALF>
__global__ void __launch_bounds__(512) gemm_mma_kernel(
    const void* __restrict__ Aptr, const __half* __restrict__ Wt_g,
    __half* __restrict__ C, int n)
{
    extern __shared__ __half sh[];
    __half* As = sh;                 // [128][SA]
    __half* Wt = sh + 128 * SA;      // [128][SA], Wt[n][k]

    int t = threadIdx.x;
    int row0 = blockIdx.x * 128;

    for (int i = t; i < F * F / 8; i += 512) {
        int r = i >> 4, c16 = i & 15;
        *(uint4*)&Wt[r * SA + c16 * 8] = ((const uint4*)Wt_g)[i];
    }

    if (A_IS_HALF) {
        const __half* A = (const __half*)Aptr;
        for (int i = t; i < 128 * F / 8; i += 512) {
            int lin = i * 8;
            int r = lin >> 7, c = lin & 127;
            uint4 v = make_uint4(0u, 0u, 0u, 0u);
            if (row0 + r < n) v = *(const uint4*)&A[(size_t)(row0 + r) * F + c];
            *(uint4*)&As[r * SA + c] = v;
        }
    } else {
        const float* A = (const float*)Aptr;
        for (int i = t; i < 128 * F / 4; i += 512) {
            int lin = i * 4;
            int r = lin >> 7, c = lin & 127;
            float4 v = make_float4(0.f, 0.f, 0.f, 0.f);
            if (row0 + r < n) v = *(const float4*)&A[(size_t)(row0 + r) * F + c];
            *(__half2*)&As[r * SA + c]     = __floats2half2_rn(v.x, v.y);
            *(__half2*)&As[r * SA + c + 2] = __floats2half2_rn(v.z, v.w);
        }
    }
    __syncthreads();

    int w = t >> 5, lane = t & 31;
    int wm = w >> 1, wn = w & 1;
    int gq = lane >> 2, tq = lane & 3;
    int m0 = wm * 16;
    int n0 = wn * 64;

    float acc[8][4];
#pragma unroll
    for (int nt = 0; nt < 8; nt++)
#pragma unroll
        for (int c = 0; c < 4; c++) acc[nt][c] = 0.f;

#pragma unroll
    for (int k0 = 0; k0 < F; k0 += 16) {
        uint32_t a0 = *(const uint32_t*)&As[(m0 + gq) * SA + k0 + tq * 2];
        uint32_t a1 = *(const uint32_t*)&As[(m0 + gq + 8) * SA + k0 + tq * 2];
        uint32_t a2 = *(const uint32_t*)&As[(m0 + gq) * SA + k0 + tq * 2 + 8];
        uint32_t a3 = *(const uint32_t*)&As[(m0 + gq + 8) * SA + k0 + tq * 2 + 8];
#pragma unroll
        for (int nt = 0; nt < 8; nt++) {
            uint32_t b0 = *(const uint32_t*)&Wt[(n0 + nt * 8 + gq) * SA + k0 + tq * 2];
            uint32_t b1 = *(const uint32_t*)&Wt[(n0 + nt * 8 + gq) * SA + k0 + tq * 2 + 8];
            asm volatile(
                "mma.sync.aligned.m16n8k16.row.col.f32.f16.f16.f32 "
                "{%0,%1,%2,%3}, {%4,%5,%6,%7}, {%8,%9}, {%0,%1,%2,%3};"
                : "+f"(acc[nt][0]), "+f"(acc[nt][1]), "+f"(acc[nt][2]), "+f"(acc[nt][3])
                : "r"(a0), "r"(a1), "r"(a2), "r"(a3), "r"(b0), "r"(b1));
        }
    }

    int r1 = row0 + m0 + gq;
    int r2 = r1 + 8;
    float d1 = (r1 < n) ? g_dis[r1] : 0.f;
    float d2 = (r2 < n) ? g_dis[r2] : 0.f;
#pragma unroll
    for (int nt = 0; nt < 8; nt++) {
        int col = n0 + nt * 8 + tq * 2;
        if (r1 < n) *(__half2*)&C[(size_t)r1 * F + col] = __floats2half2_rn(acc[nt][0] * d1, acc[nt][1] * d1);
        if (r2 < n) *(__half2*)&C[(size_t)r2 * F + col] = __floats2half2_rn(acc[nt][2] * d2, acc[nt][3] * d2);
    }
}

// ---------------- CSR gather (warp/node, pairwise HADD2 accumulate) --------
__device__ __forceinline__ void acc2(float4& s, uint2 u) {
    float2 a = __half22float2(*(const __half2*)&u.x);
    float2 b = __half22float2(*(const __half2*)&u.y);
    s.x += a.x; s.y += a.y; s.z += b.x; s.w += b.y;
}

// pair-sum in fp16 (one rounding per element), then fp32 accumulate
__device__ __forceinline__ void accp(float4& s, uint2 a, uint2 b) {
    __half2 px = __hadd2(*(const __half2*)&a.x, *(const __half2*)&b.x);
    __half2 py = __hadd2(*(const __half2*)&a.y, *(const __half2*)&b.y);
    float2 fx = __half22float2(px);
    float2 fy = __half22float2(py);
    s.x += fx.x; s.y += fx.y; s.z += fy.x; s.w += fy.y;
}

__device__ __forceinline__ float4 agg_row(const uint2* __restrict__ gp,
                                          int node, int lane) {
    float4 s = make_float4(0.f, 0.f, 0.f, 0.f);
    acc2(s, __ldg(&gp[(size_t)node * 32 + lane]));    // self loop (pre-scaled)
    int i = g_rowptr[node];
    int end = g_rowptr[node + 1];
    while (i < end && (i & 3)) {                      // peel to 16B alignment
        acc2(s, __ldg(&gp[(size_t)__ldg(&g_csr[i]) * 32 + lane]));
        i++;
    }
    for (; i + 8 <= end; i += 8) {
        int4 ia = __ldg((const int4*)&g_csr[i]);
        int4 ib = __ldg((const int4*)&g_csr[i + 4]);
        uint2 u0 = __ldg(&gp[(size_t)ia.x * 32 + lane]);
        uint2 u1 = __ldg(&gp[(size_t)ia.y * 32 + lane]);
        uint2 u2 = __ldg(&gp[(size_t)ia.z * 32 + lane]);
        uint2 u3 = __ldg(&gp[(size_t)ia.w * 32 + lane]);
        uint2 u4 = __ldg(&gp[(size_t)ib.x * 32 + lane]);
        uint2 u5 = __ldg(&gp[(size_t)ib.y * 32 + lane]);
        uint2 u6 = __ldg(&gp[(size_t)ib.z * 32 + lane]);
        uint2 u7 = __ldg(&gp[(size_t)ib.w * 32 + lane]);
        accp(s, u0, u1); accp(s, u2, u3);
        accp(s, u4, u5); accp(s, u6, u7);
    }
    if (i + 4 <= end) {
        int4 ia = __ldg((const int4*)&g_csr[i]);
        uint2 u0 = __ldg(&gp[(size_t)ia.x * 32 + lane]);
        uint2 u1 = __ldg(&gp[(size_t)ia.y * 32 + lane]);
        uint2 u2 = __ldg(&gp[(size_t)ia.z * 32 + lane]);
        uint2 u3 = __ldg(&gp[(size_t)ia.w * 32 + lane]);
        accp(s, u0, u1); accp(s, u2, u3);
        i += 4;
    }
    for (; i < end; i++) {
        acc2(s, __ldg(&gp[(size_t)__ldg(&g_csr[i]) * 32 + lane]));
    }
    return s;
}

// h1 = fp16(relu(dis*sum + b))
__global__ void __launch_bounds__(256) agg1_kernel(const float* __restrict__ b, int n) {
    int w = (blockIdx.x * blockDim.x + threadIdx.x) >> 5;
    int lane = threadIdx.x & 31;
    if (w >= n) return;
    float4 s = agg_row((const uint2*)g_t1, w, lane);
    float d = g_dis[w];
    float4 bb = __ldg((const float4*)&b[lane * 4]);
    float ox = fmaxf(fmaf(d, s.x, bb.x), 0.f);
    float oy = fmaxf(fmaf(d, s.y, bb.y), 0.f);
    float oz = fmaxf(fmaf(d, s.z, bb.z), 0.f);
    float ow = fmaxf(fmaf(d, s.w, bb.w), 0.f);
    __half2 p0 = __floats2half2_rn(ox, oy);
    __half2 p1 = __floats2half2_rn(oz, ow);
    uint2 st;
    st.x = *(uint32_t*)&p0;
    st.y = *(uint32_t*)&p1;
    ((uint2*)g_h1)[(size_t)w * 32 + lane] = st;
}

// o = relu(dis*sum + b) * inv_count; mean-pool scatter
__global__ void __launch_bounds__(256) agg2_kernel(
    const void* __restrict__ batch, const float* __restrict__ b,
    float* __restrict__ out, int n)
{
    int w = (blockIdx.x * blockDim.x + threadIdx.x) >> 5;
    int lane = threadIdx.x & 31;
    if (w >= n) return;
    float4 s = agg_row((const uint2*)g_t2, w, lane);
    float d = g_dis[w];
    float4 bb = __ldg((const float4*)&b[lane * 4]);
    long long gid = load_idx(batch, w, g_b64);
    float inv = __ldg(&g_inv[gid]);
    float ox = fmaxf(fmaf(d, s.x, bb.x), 0.f) * inv;
    float oy = fmaxf(fmaf(d, s.y, bb.y), 0.f) * inv;
    float oz = fmaxf(fmaf(d, s.z, bb.z), 0.f) * inv;
    float ow = fmaxf(fmaf(d, s.w, bb.w), 0.f) * inv;
    float* p = &out[(size_t)gid * F + lane * 4];
    asm volatile("red.global.add.v4.f32 [%0], {%1,%2,%3,%4};"
                 :: "l"(p), "f"(ox), "f"(oy), "f"(oz), "f"(ow) : "memory");
}

// ---------------- launch ----------------
extern "C" void kernel_launch(void* const* d_in, const int* in_sizes, int n_in,
                              void* d_out, int out_size) {
    const float* x    = (const float*)d_in[0];
    const void*  edge = d_in[1];
    const void*  batch= d_in[2];
    const float* W1   = (const float*)d_in[3];
    const float* b1   = (const float*)d_in[4];
    const float* W2   = (const float*)d_in[5];
    const float* b2   = (const float*)d_in[6];
    float* out = (float*)d_out;

    int N = in_sizes[0] / F;
    int E = in_sizes[1] / 2;
    int G = out_size / F;

    void *p_t1, *p_h1, *p_t2, *p_w1t, *p_w2t;
    cudaGetSymbolAddress(&p_t1, g_t1);
    cudaGetSymbolAddress(&p_h1, g_h1);
    cudaGetSymbolAddress(&p_t2, g_t2);
    cudaGetSymbolAddress(&p_w1t, g_w1t);
    cudaGetSymbolAddress(&p_w2t, g_w2t);

    const int SMEM = 2 * 128 * SA * (int)sizeof(__half);   // 69632 bytes
    cudaFuncSetAttribute(gemm_mma_kernel<false>, cudaFuncAttributeMaxDynamicSharedMemorySize, SMEM);
    cudaFuncSetAttribute(gemm_mma_kernel<true>,  cudaFuncAttributeMaxDynamicSharedMemorySize, SMEM);

    const int TB = 256;
    int gemm_grid = (N + 127) / 128;
    int agg_grid = (N + 7) / 8;

    // launches: 0 prep1, 1 prep2, 2 gemm1, 3 agg1 (profiled), 4 gemm2, 5 agg2
    prep1_kernel<<<PREP_BLOCKS, PREP_THREADS>>>(edge, batch, W1, W2, out, G * F, N, E);
    prep2_kernel<<<PREP_BLOCKS, PREP_THREADS>>>(edge, N, E);
    gemm_mma_kernel<false><<<gemm_grid, 512, SMEM>>>(x, (const __half*)p_w1t, (__half*)p_t1, N);
    agg1_kernel<<<agg_grid, TB>>>(b1, N);
    gemm_mma_kernel<true><<<gemm_grid, 512, SMEM>>>(p_h1, (const __half*)p_w2t, (__half*)p_t2, N);
    agg2_kernel<<<agg_grid, TB>>>(batch, b2, out, N);
}

// round 14
// speedup vs baseline: 1.1335x; 1.0410x over previous
#include <cuda_runtime.h>
#include <cuda_fp16.h>
#include <cuda_bf16.h>
#include <stdint.h>

// ---------------- static scratch (no allocation allowed) ----------------
#define N_MAX 100352          // >= N=100000 (+1 dummy zero row)
#define E_MAX 2200000         // >= E + 3*N (CSR padding to multiple of 4)
#define F 128                 // feature dim
#define SA 136                // padded smem row stride (halves)
#define PREP_BLOCKS 128
#define PREP_THREADS 1024

__device__ __align__(16) static __half g_t1[(size_t)N_MAX * F];  // (x@W1)*dis (fp16)
__device__ __align__(16) static __half g_h1[(size_t)N_MAX * F];  // relu layer-1 out (fp16)
__device__ __align__(16) static __half g_t2[(size_t)N_MAX * F];  // (h1@W2)*dis (fp16)
__device__ __align__(16) static __half g_w1t[F * F];             // W1^T fp16 [n][k]
__device__ __align__(16) static __half g_w2t[F * F];             // W2^T fp16 [n][k]
__device__ __align__(16) static float g_dis[N_MAX];
__device__ static int   g_degc[N_MAX];
__device__ static int   g_rowptr[N_MAX + 4];     // PADDED offsets (multiples of 4)
__device__ static int   g_rank[E_MAX];
__device__ __align__(16) static int g_csr[E_MAX];
__device__ static int   g_part[PREP_BLOCKS];
__device__ static int   g_gstart[1024];
__device__ static int   g_gend[1024];
__device__ static float g_inv[1024];
__device__ static int   g_e64;
__device__ static int   g_b64;
__device__ static int   g_bar_cnt[8];
__device__ static int   g_bar_gen[8];

// ---------------- software grid barrier (all blocks co-resident) ----------
__device__ __forceinline__ void gbar(int slot, int nblk) {
    __syncthreads();
    if (threadIdx.x == 0) {
        __threadfence();
        int gen = atomicAdd(&g_bar_gen[slot], 0);
        if (atomicAdd(&g_bar_cnt[slot], 1) == nblk - 1) {
            atomicExch(&g_bar_cnt[slot], 0);
            __threadfence();
            atomicAdd(&g_bar_gen[slot], 1);
        } else {
            while (atomicAdd(&g_bar_gen[slot], 0) == gen) {}
        }
        __threadfence();
    }
    __syncthreads();
}

__device__ __forceinline__ long long load_idx(const void* p, long long i, int is64) {
    if (is64) return ((const long long*)p)[i];
    return (long long)((const int*)p)[i];
}

__device__ __forceinline__ void load_pair(const void* p, long long i, int is64,
                                          int& v0, int& v1) {
    if (is64) {
        longlong2 v = ((const longlong2*)p)[i >> 1];
        v0 = (int)v.x; v1 = (int)v.y;
    } else {
        int2 v = ((const int2*)p)[i >> 1];
        v0 = v.x; v1 = v.y;
    }
}

// ---------------- kernel 1: detect + zero + Wt + deg/rank + graph bounds ---
__global__ void __launch_bounds__(PREP_THREADS) prep1_kernel(
    const void* __restrict__ edge, const void* __restrict__ batch,
    const float* __restrict__ W1, const float* __restrict__ W2,
    float* __restrict__ out, int outw, int n, int E)
{
    const int T = PREP_BLOCKS * PREP_THREADS;
    int t = threadIdx.x;
    int tid = blockIdx.x * PREP_THREADS + t;

    if (blockIdx.x < 2) {
        __shared__ int any;
        if (t == 0) any = 0;
        __syncthreads();
        const int* a = (blockIdx.x == 0) ? (const int*)edge : (const int*)batch;
        int local = 0;
        for (int i = 1 + 2 * t; i < 2048; i += 2 * PREP_THREADS) local |= a[i];
        if (local) atomicOr(&any, 1);
        __syncthreads();
        if (t == 0) {
            int is64 = (any == 0) ? 1 : 0;
            if (blockIdx.x == 0) g_e64 = is64; else g_b64 = is64;
        }
    }
    if (blockIdx.x == 2) {
        for (int i = t; i < F * F; i += PREP_THREADS) {
            int k = i >> 7, nn = i & 127;
            g_w1t[nn * F + k] = __float2half(W1[i]);
        }
    }
    if (blockIdx.x == 3) {
        for (int i = t; i < F * F; i += PREP_THREADS) {
            int k = i >> 7, nn = i & 127;
            g_w2t[nn * F + k] = __float2half(W2[i]);
        }
    }
    // zero dummy feature row n (target of CSR padding entries)
    if (blockIdx.x == 4) {
        for (int i = t; i < F / 2; i += PREP_THREADS) {
            ((uint32_t*)(g_t1 + (size_t)n * F))[i] = 0u;
            ((uint32_t*)(g_t2 + (size_t)n * F))[i] = 0u;
        }
    }
    for (int i = tid; i < n; i += T) g_degc[i] = 0;
    for (int i = tid; i < outw; i += T) out[i] = 0.f;
    for (int i = tid; i < 1024; i += T) { g_gstart[i] = 0; g_gend[i] = 0; }
    gbar(0, PREP_BLOCKS);

    // ---- degree histogram + per-edge rank ----
    {
        int is64 = g_e64;
        int epairs = (E + 1) / 2;
        bool even = ((E & 1) == 0);
        for (int p = tid; p < epairs; p += T) {
            int e0 = 2 * p;
            if (even || e0 + 1 < E) {
                int d0, d1;
                load_pair(edge, (long long)E + e0, is64, d0, d1);
                g_rank[e0]     = atomicAdd(&g_degc[d0], 1);
                g_rank[e0 + 1] = atomicAdd(&g_degc[d1], 1);
            } else {
                int d0 = (int)load_idx(edge, (long long)E + e0, is64);
                g_rank[e0] = atomicAdd(&g_degc[d0], 1);
            }
        }
    }
    // ---- graph boundary detection on sorted batch ----
    {
        int is64b = g_b64;
        for (int i = tid; i < n; i += T) {
            int b = (int)load_idx(batch, i, is64b);
            int prev = (i > 0) ? (int)load_idx(batch, (long long)i - 1, is64b) : -1;
            int next = (i + 1 < n) ? (int)load_idx(batch, (long long)i + 1, is64b) : -2;
            if (b != prev) g_gstart[b] = i;
            if (b != next) g_gend[b] = i + 1;
        }
    }
}

// ---------------- kernel 2: padded scan(+dis) + inv-counts + CSR fill ------
__global__ void __launch_bounds__(PREP_THREADS) prep2_kernel(
    const void* __restrict__ edge, int n, int E, int zrow)
{
    const int T = PREP_BLOCKS * PREP_THREADS;
    int t = threadIdx.x;
    int tid = blockIdx.x * PREP_THREADS + t;

    if (blockIdx.x == PREP_BLOCKS - 1 && t < 1024) {
        int c = g_gend[t] - g_gstart[t];
        g_inv[t] = 1.f / (float)max(c, 1);
    }

    // ---- block-local scan of PADDED degrees + dis ----
    {
        __shared__ int sh[PREP_THREADS];
        int i = tid;
        int v = (i < n) ? g_degc[i] : 0;
        int pv = (v + 3) & ~3;                          // pad to multiple of 4
        if (i < n) g_dis[i] = rsqrtf((float)(v + 1));   // +1 self loop
        sh[t] = pv;
        __syncthreads();
        for (int off = 1; off < PREP_THREADS; off <<= 1) {
            int tmp = (t >= off) ? sh[t - off] : 0;
            __syncthreads();
            sh[t] += tmp;
            __syncthreads();
        }
        if (i < n) g_rowptr[i] = sh[t] - pv;
        if (t == PREP_THREADS - 1) g_part[blockIdx.x] = sh[PREP_THREADS - 1];
    }
    gbar(1, PREP_BLOCKS);

    if (blockIdx.x == 0) {
        __shared__ int sp[PREP_BLOCKS];
        int v = (t < PREP_BLOCKS) ? g_part[t] : 0;
        if (t < PREP_BLOCKS) sp[t] = v;
        __syncthreads();
        for (int off = 1; off < PREP_BLOCKS; off <<= 1) {
            int tmp = (t < PREP_BLOCKS && t >= off) ? sp[t - off] : 0;
            __syncthreads();
            if (t < PREP_BLOCKS) sp[t] += tmp;
            __syncthreads();
        }
        if (t < PREP_BLOCKS) g_part[t] = sp[t] - v;
    }
    gbar(2, PREP_BLOCKS);

    {
        int i = tid;
        if (i < n) {
            int r = g_rowptr[i] + g_part[blockIdx.x];
            g_rowptr[i] = r;
            if (i == n - 1) g_rowptr[n] = r + ((g_degc[i] + 3) & ~3);
        }
    }
    gbar(3, PREP_BLOCKS);

    // ---- CSR fill (atomic-free) + padding fill ----
    {
        int is64 = g_e64;
        int epairs = (E + 1) / 2;
        bool even = ((E & 1) == 0);
        for (int p = tid; p < epairs; p += T) {
            int e0 = 2 * p;
            if (even || e0 + 1 < E) {
                int s0, s1, d0, d1;
                load_pair(edge, (long long)e0, is64, s0, s1);
                load_pair(edge, (long long)E + e0, is64, d0, d1);
                int2 rk = *(const int2*)&g_rank[e0];
                g_csr[g_rowptr[d0] + rk.x] = s0;
                g_csr[g_rowptr[d1] + rk.y] = s1;
            } else {
                int s0 = (int)load_idx(edge, (long long)e0, is64);
                int d0 = (int)load_idx(edge, (long long)E + e0, is64);
                g_csr[g_rowptr[d0] + g_rank[e0]] = s0;
            }
        }
        // pad each row's tail with the dummy zero row
        for (int i = tid; i < n; i += T) {
            int st = g_rowptr[i];
            int deg = g_degc[i];
            int pdeg = (deg + 3) & ~3;
            for (int j = deg; j < pdeg; j++) g_csr[st + j] = zrow;
        }
    }
}

// ---------------- tensor-core GEMM: C = fp16((A @ W) * dis[row]) -----------
template<bool A_IS_HALF>
__global__ void __launch_bounds__(512) gemm_mma_kernel(
    const void* __restrict__ Aptr, const __half* __restrict__ Wt_g,
    __half* __restrict__ C, int n)
{
    extern __shared__ __half sh[];
    __half* As = sh;                 // [128][SA]
    __half* Wt = sh + 128 * SA;      // [128][SA], Wt[n][k]

    int t = threadIdx.x;
    int row0 = blockIdx.x * 128;

    for (int i = t; i < F * F / 8; i += 512) {
        int r = i >> 4, c16 = i & 15;
        *(uint4*)&Wt[r * SA + c16 * 8] = ((const uint4*)Wt_g)[i];
    }

    if (A_IS_HALF) {
        const __half* A = (const __half*)Aptr;
        for (int i = t; i < 128 * F / 8; i += 512) {
            int lin = i * 8;
            int r = lin >> 7, c = lin & 127;
            uint4 v = make_uint4(0u, 0u, 0u, 0u);
            if (row0 + r < n) v = *(const uint4*)&A[(size_t)(row0 + r) * F + c];
            *(uint4*)&As[r * SA + c] = v;
        }
    } else {
        const float* A = (const float*)Aptr;
        for (int i = t; i < 128 * F / 4; i += 512) {
            int lin = i * 4;
            int r = lin >> 7, c = lin & 127;
            float4 v = make_float4(0.f, 0.f, 0.f, 0.f);
            if (row0 + r < n) v = *(const float4*)&A[(size_t)(row0 + r) * F + c];
            *(__half2*)&As[r * SA + c]     = __floats2half2_rn(v.x, v.y);
            *(__half2*)&As[r * SA + c + 2] = __floats2half2_rn(v.z, v.w);
        }
    }
    __syncthreads();

    int w = t >> 5, lane = t & 31;
    int wm = w >> 1, wn = w & 1;
    int gq = lane >> 2, tq = lane & 3;
    int m0 = wm * 16;
    int n0 = wn * 64;

    float acc[8][4];
#pragma unroll
    for (int nt = 0; nt < 8; nt++)
#pragma unroll
        for (int c = 0; c < 4; c++) acc[nt][c] = 0.f;

#pragma unroll
    for (int k0 = 0; k0 < F; k0 += 16) {
        uint32_t a0 = *(const uint32_t*)&As[(m0 + gq) * SA + k0 + tq * 2];
        uint32_t a1 = *(const uint32_t*)&As[(m0 + gq + 8) * SA + k0 + tq * 2];
        uint32_t a2 = *(const uint32_t*)&As[(m0 + gq) * SA + k0 + tq * 2 + 8];
        uint32_t a3 = *(const uint32_t*)&As[(m0 + gq + 8) * SA + k0 + tq * 2 + 8];
#pragma unroll
        for (int nt = 0; nt < 8; nt++) {
            uint32_t b0 = *(const uint32_t*)&Wt[(n0 + nt * 8 + gq) * SA + k0 + tq * 2];
            uint32_t b1 = *(const uint32_t*)&Wt[(n0 + nt * 8 + gq) * SA + k0 + tq * 2 + 8];
            asm volatile(
                "mma.sync.aligned.m16n8k16.row.col.f32.f16.f16.f32 "
                "{%0,%1,%2,%3}, {%4,%5,%6,%7}, {%8,%9}, {%0,%1,%2,%3};"
                : "+f"(acc[nt][0]), "+f"(acc[nt][1]), "+f"(acc[nt][2]), "+f"(acc[nt][3])
                : "r"(a0), "r"(a1), "r"(a2), "r"(a3), "r"(b0), "r"(b1));
        }
    }

    int r1 = row0 + m0 + gq;
    int r2 = r1 + 8;
    float d1 = (r1 < n) ? g_dis[r1] : 0.f;
    float d2 = (r2 < n) ? g_dis[r2] : 0.f;
#pragma unroll
    for (int nt = 0; nt < 8; nt++) {
        int col = n0 + nt * 8 + tq * 2;
        if (r1 < n) *(__half2*)&C[(size_t)r1 * F + col] = __floats2half2_rn(acc[nt][0] * d1, acc[nt][1] * d1);
        if (r2 < n) *(__half2*)&C[(size_t)r2 * F + col] = __floats2half2_rn(acc[nt][2] * d2, acc[nt][3] * d2);
    }
}

// ---------------- CSR gather (warp/node, quad fp16 tree, aligned) ----------
__device__ __forceinline__ void acc2(float4& s, uint2 u) {
    float2 a = __half22float2(*(const __half2*)&u.x);
    float2 b = __half22float2(*(const __half2*)&u.y);
    s.x += a.x; s.y += a.y; s.z += b.x; s.w += b.y;
}

// depth-2 fp16 tree over 4 gathered rows, then fp32 accumulate
__device__ __forceinline__ void accq(float4& s, uint2 u0, uint2 u1, uint2 u2, uint2 u3) {
    __half2 ax = __hadd2(*(const __half2*)&u0.x, *(const __half2*)&u1.x);
    __half2 ay = __hadd2(*(const __half2*)&u0.y, *(const __half2*)&u1.y);
    __half2 bx = __hadd2(*(const __half2*)&u2.x, *(const __half2*)&u3.x);
    __half2 by = __hadd2(*(const __half2*)&u2.y, *(const __half2*)&u3.y);
    __half2 qx = __hadd2(ax, bx);
    __half2 qy = __hadd2(ay, by);
    float2 fx = __half22float2(qx);
    float2 fy = __half22float2(qy);
    s.x += fx.x; s.y += fx.y; s.z += fy.x; s.w += fy.y;
}

__device__ __forceinline__ float4 agg_row(const uint2* __restrict__ gp,
                                          int node, int lane) {
    float4 s = make_float4(0.f, 0.f, 0.f, 0.f);
    acc2(s, __ldg(&gp[(size_t)node * 32 + lane]));    // self loop (pre-scaled)
    int i = g_rowptr[node];
    int end = g_rowptr[node + 1];                     // padded: (end-i) % 4 == 0
    for (; i + 8 <= end; i += 8) {
        int4 ia = __ldg((const int4*)&g_csr[i]);
        int4 ib = __ldg((const int4*)&g_csr[i + 4]);
        uint2 u0 = __ldg(&gp[(size_t)ia.x * 32 + lane]);
        uint2 u1 = __ldg(&gp[(size_t)ia.y * 32 + lane]);
        uint2 u2 = __ldg(&gp[(size_t)ia.z * 32 + lane]);
        uint2 u3 = __ldg(&gp[(size_t)ia.w * 32 + lane]);
        uint2 u4 = __ldg(&gp[(size_t)ib.x * 32 + lane]);
        uint2 u5 = __ldg(&gp[(size_t)ib.y * 32 + lane]);
        uint2 u6 = __ldg(&gp[(size_t)ib.z * 32 + lane]);
        uint2 u7 = __ldg(&gp[(size_t)ib.w * 32 + lane]);
        accq(s, u0, u1, u2, u3);
        accq(s, u4, u5, u6, u7);
    }
    if (i < end) {                                    // exactly one 4-block
        int4 ia = __ldg((const int4*)&g_csr[i]);
        uint2 u0 = __ldg(&gp[(size_t)ia.x * 32 + lane]);
        uint2 u1 = __ldg(&gp[(size_t)ia.y * 32 + lane]);
        uint2 u2 = __ldg(&gp[(size_t)ia.z * 32 + lane]);
        uint2 u3 = __ldg(&gp[(size_t)ia.w * 32 + lane]);
        accq(s, u0, u1, u2, u3);
    }
    return s;
}

// h1 = fp16(relu(dis*sum + b))
__global__ void __launch_bounds__(256) agg1_kernel(const float* __restrict__ b, int n) {
    int w = (blockIdx.x * blockDim.x + threadIdx.x) >> 5;
    int lane = threadIdx.x & 31;
    if (w >= n) return;
    float4 s = agg_row((const uint2*)g_t1, w, lane);
    float d = g_dis[w];
    float4 bb = __ldg((const float4*)&b[lane * 4]);
    float ox = fmaxf(fmaf(d, s.x, bb.x), 0.f);
    float oy = fmaxf(fmaf(d, s.y, bb.y), 0.f);
    float oz = fmaxf(fmaf(d, s.z, bb.z), 0.f);
    float ow = fmaxf(fmaf(d, s.w, bb.w), 0.f);
    __half2 p0 = __floats2half2_rn(ox, oy);
    __half2 p1 = __floats2half2_rn(oz, ow);
    uint2 st;
    st.x = *(uint32_t*)&p0;
    st.y = *(uint32_t*)&p1;
    ((uint2*)g_h1)[(size_t)w * 32 + lane] = st;
}

// o = relu(dis*sum + b) * inv_count; mean-pool scatter
__global__ void __launch_bounds__(256) agg2_kernel(
    const void* __restrict__ batch, const float* __restrict__ b,
    float* __restrict__ out, int n)
{
    int w = (blockIdx.x * blockDim.x + threadIdx.x) >> 5;
    int lane = threadIdx.x & 31;
    if (w >= n) return;
    float4 s = agg_row((const uint2*)g_t2, w, lane);
    float d = g_dis[w];
    float4 bb = __ldg((const float4*)&b[lane * 4]);
    long long gid = load_idx(batch, w, g_b64);
    float inv = __ldg(&g_inv[gid]);
    float ox = fmaxf(fmaf(d, s.x, bb.x), 0.f) * inv;
    float oy = fmaxf(fmaf(d, s.y, bb.y), 0.f) * inv;
    float oz = fmaxf(fmaf(d, s.z, bb.z), 0.f) * inv;
    float ow = fmaxf(fmaf(d, s.w, bb.w), 0.f) * inv;
    float* p = &out[(size_t)gid * F + lane * 4];
    asm volatile("red.global.add.v4.f32 [%0], {%1,%2,%3,%4};"
                 :: "l"(p), "f"(ox), "f"(oy), "f"(oz), "f"(ow) : "memory");
}

// ---------------- launch ----------------
extern "C" void kernel_launch(void* const* d_in, const int* in_sizes, int n_in,
                              void* d_out, int out_size) {
    const float* x    = (const float*)d_in[0];
    const void*  edge = d_in[1];
    const void*  batch= d_in[2];
    const float* W1   = (const float*)d_in[3];
    const float* b1   = (const float*)d_in[4];
    const float* W2   = (const float*)d_in[5];
    const float* b2   = (const float*)d_in[6];
    float* out = (float*)d_out;

    int N = in_sizes[0] / F;
    int E = in_sizes[1] / 2;
    int G = out_size / F;

    void *p_t1, *p_h1, *p_t2, *p_w1t, *p_w2t;
    cudaGetSymbolAddress(&p_t1, g_t1);
    cudaGetSymbolAddress(&p_h1, g_h1);
    cudaGetSymbolAddress(&p_t2, g_t2);
    cudaGetSymbolAddress(&p_w1t, g_w1t);
    cudaGetSymbolAddress(&p_w2t, g_w2t);

    const int SMEM = 2 * 128 * SA * (int)sizeof(__half);   // 69632 bytes
    cudaFuncSetAttribute(gemm_mma_kernel<false>, cudaFuncAttributeMaxDynamicSharedMemorySize, SMEM);
    cudaFuncSetAttribute(gemm_mma_kernel<true>,  cudaFuncAttributeMaxDynamicSharedMemorySize, SMEM);

    const int TB = 256;
    int gemm_grid = (N + 127) / 128;
    int agg_grid = (N + 7) / 8;

    // launches: 0 prep1, 1 prep2, 2 gemm1, 3 agg1 (profiled), 4 gemm2, 5 agg2
    prep1_kernel<<<PREP_BLOCKS, PREP_THREADS>>>(edge, batch, W1, W2, out, G * F, N, E);
    prep2_kernel<<<PREP_BLOCKS, PREP_THREADS>>>(edge, N, E, N);
    gemm_mma_kernel<false><<<gemm_grid, 512, SMEM>>>(x, (const __half*)p_w1t, (__half*)p_t1, N);
    agg1_kernel<<<agg_grid, TB>>>(b1, N);
    gemm_mma_kernel<true><<<gemm_grid, 512, SMEM>>>(p_h1, (const __half*)p_w2t, (__half*)p_t2, N);
    agg2_kernel<<<agg_grid, TB>>>(batch, b2, out, N);
}

// round 15
// speedup vs baseline: 1.1387x; 1.0046x over previous
#include <cuda_runtime.h>
#include <cuda_fp16.h>
#include <cuda_bf16.h>
#include <stdint.h>

// ---------------- static scratch (no allocation allowed) ----------------
#define N_MAX 100352          // >= N=100000 (+1 dummy zero row)
#define E_MAX 2200000         // >= E + 3*N (CSR padding to multiple of 4)
#define F 128                 // feature dim
#define SA 136                // padded smem row stride (halves)
#define PREP_BLOCKS 128
#define PREP_THREADS 1024

__device__ __align__(16) static __half g_t1[(size_t)N_MAX * F];  // (x@W1)*dis (fp16)
__device__ __align__(16) static __half g_h1[(size_t)N_MAX * F];  // relu layer-1 out (fp16)
__device__ __align__(16) static __half g_t2[(size_t)N_MAX * F];  // (h1@W2)*dis (fp16)
__device__ __align__(16) static __half g_w1t[F * F];             // W1^T fp16 [n][k]
__device__ __align__(16) static __half g_w2t[F * F];             // W2^T fp16 [n][k]
__device__ __align__(16) static float g_dis[N_MAX];
__device__ static int   g_degc[N_MAX];
__device__ static int   g_rowptr[N_MAX + 4];     // PADDED offsets (multiples of 4)
__device__ static int   g_rank[E_MAX];
__device__ __align__(16) static int g_csr[E_MAX];
__device__ static int   g_part[PREP_BLOCKS];
__device__ static int   g_gstart[1024];
__device__ static int   g_gend[1024];
__device__ static float g_inv[1024];
__device__ static int   g_e64;
__device__ static int   g_b64;
__device__ static int   g_bar_cnt[8];
__device__ static int   g_bar_gen[8];

// ---------------- software grid barrier (all blocks co-resident) ----------
__device__ __forceinline__ void gbar(int slot, int nblk) {
    __syncthreads();
    if (threadIdx.x == 0) {
        __threadfence();
        int gen = atomicAdd(&g_bar_gen[slot], 0);
        if (atomicAdd(&g_bar_cnt[slot], 1) == nblk - 1) {
            atomicExch(&g_bar_cnt[slot], 0);
            __threadfence();
            atomicAdd(&g_bar_gen[slot], 1);
        } else {
            while (atomicAdd(&g_bar_gen[slot], 0) == gen) {}
        }
        __threadfence();
    }
    __syncthreads();
}

__device__ __forceinline__ long long load_idx(const void* p, long long i, int is64) {
    if (is64) return ((const long long*)p)[i];
    return (long long)((const int*)p)[i];
}

__device__ __forceinline__ void load_pair(const void* p, long long i, int is64,
                                          int& v0, int& v1) {
    if (is64) {
        longlong2 v = ((const longlong2*)p)[i >> 1];
        v0 = (int)v.x; v1 = (int)v.y;
    } else {
        int2 v = ((const int2*)p)[i >> 1];
        v0 = v.x; v1 = v.y;
    }
}

// ---------------- kernel 1: detect + zero + Wt + deg/rank + graph bounds ---
__global__ void __launch_bounds__(PREP_THREADS) prep1_kernel(
    const void* __restrict__ edge, const void* __restrict__ batch,
    const float* __restrict__ W1, const float* __restrict__ W2,
    float* __restrict__ out, int outw, int n, int E)
{
    const int T = PREP_BLOCKS * PREP_THREADS;
    int t = threadIdx.x;
    int tid = blockIdx.x * PREP_THREADS + t;

    if (blockIdx.x < 2) {
        __shared__ int any;
        if (t == 0) any = 0;
        __syncthreads();
        const int* a = (blockIdx.x == 0) ? (const int*)edge : (const int*)batch;
        int local = 0;
        for (int i = 1 + 2 * t; i < 2048; i += 2 * PREP_THREADS) local |= a[i];
        if (local) atomicOr(&any, 1);
        __syncthreads();
        if (t == 0) {
            int is64 = (any == 0) ? 1 : 0;
            if (blockIdx.x == 0) g_e64 = is64; else g_b64 = is64;
        }
    }
    if (blockIdx.x == 2) {
        for (int i = t; i < F * F; i += PREP_THREADS) {
            int k = i >> 7, nn = i & 127;
            g_w1t[nn * F + k] = __float2half(W1[i]);
        }
    }
    if (blockIdx.x == 3) {
        for (int i = t; i < F * F; i += PREP_THREADS) {
            int k = i >> 7, nn = i & 127;
            g_w2t[nn * F + k] = __float2half(W2[i]);
        }
    }
    if (blockIdx.x == 4) {
        for (int i = t; i < F / 2; i += PREP_THREADS) {
            ((uint32_t*)(g_t1 + (size_t)n * F))[i] = 0u;
            ((uint32_t*)(g_t2 + (size_t)n * F))[i] = 0u;
        }
    }
    for (int i = tid; i < n; i += T) g_degc[i] = 0;
    for (int i = tid; i < outw; i += T) out[i] = 0.f;
    for (int i = tid; i < 1024; i += T) { g_gstart[i] = 0; g_gend[i] = 0; }
    gbar(0, PREP_BLOCKS);

    // ---- degree histogram + per-edge rank ----
    {
        int is64 = g_e64;
        int epairs = (E + 1) / 2;
        bool even = ((E & 1) == 0);
        for (int p = tid; p < epairs; p += T) {
            int e0 = 2 * p;
            if (even || e0 + 1 < E) {
                int d0, d1;
                load_pair(edge, (long long)E + e0, is64, d0, d1);
                g_rank[e0]     = atomicAdd(&g_degc[d0], 1);
                g_rank[e0 + 1] = atomicAdd(&g_degc[d1], 1);
            } else {
                int d0 = (int)load_idx(edge, (long long)E + e0, is64);
                g_rank[e0] = atomicAdd(&g_degc[d0], 1);
            }
        }
    }
    // ---- graph boundary detection on sorted batch ----
    {
        int is64b = g_b64;
        for (int i = tid; i < n; i += T) {
            int b = (int)load_idx(batch, i, is64b);
            int prev = (i > 0) ? (int)load_idx(batch, (long long)i - 1, is64b) : -1;
            int next = (i + 1 < n) ? (int)load_idx(batch, (long long)i + 1, is64b) : -2;
            if (b != prev) g_gstart[b] = i;
            if (b != next) g_gend[b] = i + 1;
        }
    }
}

// ---------------- kernel 2: padded scan(+dis) + inv-counts + CSR fill ------
__global__ void __launch_bounds__(PREP_THREADS) prep2_kernel(
    const void* __restrict__ edge, int n, int E, int zrow)
{
    const int T = PREP_BLOCKS * PREP_THREADS;
    int t = threadIdx.x;
    int tid = blockIdx.x * PREP_THREADS + t;

    if (blockIdx.x == PREP_BLOCKS - 1 && t < 1024) {
        int c = g_gend[t] - g_gstart[t];
        g_inv[t] = 1.f / (float)max(c, 1);
    }

    {
        __shared__ int sh[PREP_THREADS];
        int i = tid;
        int v = (i < n) ? g_degc[i] : 0;
        int pv = (v + 3) & ~3;                          // pad to multiple of 4
        if (i < n) g_dis[i] = rsqrtf((float)(v + 1));   // +1 self loop
        sh[t] = pv;
        __syncthreads();
        for (int off = 1; off < PREP_THREADS; off <<= 1) {
            int tmp = (t >= off) ? sh[t - off] : 0;
            __syncthreads();
            sh[t] += tmp;
            __syncthreads();
        }
        if (i < n) g_rowptr[i] = sh[t] - pv;
        if (t == PREP_THREADS - 1) g_part[blockIdx.x] = sh[PREP_THREADS - 1];
    }
    gbar(1, PREP_BLOCKS);

    if (blockIdx.x == 0) {
        __shared__ int sp[PREP_BLOCKS];
        int v = (t < PREP_BLOCKS) ? g_part[t] : 0;
        if (t < PREP_BLOCKS) sp[t] = v;
        __syncthreads();
        for (int off = 1; off < PREP_BLOCKS; off <<= 1) {
            int tmp = (t < PREP_BLOCKS && t >= off) ? sp[t - off] : 0;
            __syncthreads();
            if (t < PREP_BLOCKS) sp[t] += tmp;
            __syncthreads();
        }
        if (t < PREP_BLOCKS) g_part[t] = sp[t] - v;
    }
    gbar(2, PREP_BLOCKS);

    {
        int i = tid;
        if (i < n) {
            int r = g_rowptr[i] + g_part[blockIdx.x];
            g_rowptr[i] = r;
            if (i == n - 1) g_rowptr[n] = r + ((g_degc[i] + 3) & ~3);
        }
    }
    gbar(3, PREP_BLOCKS);

    // ---- CSR fill (atomic-free) + padding fill ----
    {
        int is64 = g_e64;
        int epairs = (E + 1) / 2;
        bool even = ((E & 1) == 0);
        for (int p = tid; p < epairs; p += T) {
            int e0 = 2 * p;
            if (even || e0 + 1 < E) {
                int s0, s1, d0, d1;
                load_pair(edge, (long long)e0, is64, s0, s1);
                load_pair(edge, (long long)E + e0, is64, d0, d1);
                int2 rk = *(const int2*)&g_rank[e0];
                g_csr[g_rowptr[d0] + rk.x] = s0;
                g_csr[g_rowptr[d1] + rk.y] = s1;
            } else {
                int s0 = (int)load_idx(edge, (long long)e0, is64);
                int d0 = (int)load_idx(edge, (long long)E + e0, is64);
                g_csr[g_rowptr[d0] + g_rank[e0]] = s0;
            }
        }
        for (int i = tid; i < n; i += T) {
            int st = g_rowptr[i];
            int deg = g_degc[i];
            int pdeg = (deg + 3) & ~3;
            for (int j = deg; j < pdeg; j++) g_csr[st + j] = zrow;
        }
    }
}

// ---------------- tensor-core GEMM: C = fp16((A @ W) * dis[row]) -----------
template<bool A_IS_HALF>
__global__ void __launch_bounds__(512) gemm_mma_kernel(
    const void* __restrict__ Aptr, const __half* __restrict__ Wt_g,
    __half* __restrict__ C, int n)
{
    extern __shared__ __half sh[];
    __half* As = sh;                 // [128][SA]
    __half* Wt = sh + 128 * SA;      // [128][SA], Wt[n][k]

    int t = threadIdx.x;
    int row0 = blockIdx.x * 128;

    for (int i = t; i < F * F / 8; i += 512) {
        int r = i >> 4, c16 = i & 15;
        *(uint4*)&Wt[r * SA + c16 * 8] = ((const uint4*)Wt_g)[i];
    }

    if (A_IS_HALF) {
        const __half* A = (const __half*)Aptr;
        for (int i = t; i < 128 * F / 8; i += 512) {
            int lin = i * 8;
            int r = lin >> 7, c = lin & 127;
            uint4 v = make_uint4(0u, 0u, 0u, 0u);
            if (row0 + r < n) v = *(const uint4*)&A[(size_t)(row0 + r) * F + c];
            *(uint4*)&As[r * SA + c] = v;
        }
    } else {
        const float* A = (const float*)Aptr;
        for (int i = t; i < 128 * F / 4; i += 512) {
            int lin = i * 4;
            int r = lin >> 7, c = lin & 127;
            float4 v = make_float4(0.f, 0.f, 0.f, 0.f);
            if (row0 + r < n) v = *(const float4*)&A[(size_t)(row0 + r) * F + c];
            *(__half2*)&As[r * SA + c]     = __floats2half2_rn(v.x, v.y);
            *(__half2*)&As[r * SA + c + 2] = __floats2half2_rn(v.z, v.w);
        }
    }
    __syncthreads();

    int w = t >> 5, lane = t & 31;
    int wm = w >> 1, wn = w & 1;
    int gq = lane >> 2, tq = lane & 3;
    int m0 = wm * 16;
    int n0 = wn * 64;

    float acc[8][4];
#pragma unroll
    for (int nt = 0; nt < 8; nt++)
#pragma unroll
        for (int c = 0; c < 4; c++) acc[nt][c] = 0.f;

#pragma unroll
    for (int k0 = 0; k0 < F; k0 += 16) {
        uint32_t a0 = *(const uint32_t*)&As[(m0 + gq) * SA + k0 + tq * 2];
        uint32_t a1 = *(const uint32_t*)&As[(m0 + gq + 8) * SA + k0 + tq * 2];
        uint32_t a2 = *(const uint32_t*)&As[(m0 + gq) * SA + k0 + tq * 2 + 8];
        uint32_t a3 = *(const uint32_t*)&As[(m0 + gq + 8) * SA + k0 + tq * 2 + 8];
#pragma unroll
        for (int nt = 0; nt < 8; nt++) {
            uint32_t b0 = *(const uint32_t*)&Wt[(n0 + nt * 8 + gq) * SA + k0 + tq * 2];
            uint32_t b1 = *(const uint32_t*)&Wt[(n0 + nt * 8 + gq) * SA + k0 + tq * 2 + 8];
            asm volatile(
                "mma.sync.aligned.m16n8k16.row.col.f32.f16.f16.f32 "
                "{%0,%1,%2,%3}, {%4,%5,%6,%7}, {%8,%9}, {%0,%1,%2,%3};"
                : "+f"(acc[nt][0]), "+f"(acc[nt][1]), "+f"(acc[nt][2]), "+f"(acc[nt][3])
                : "r"(a0), "r"(a1), "r"(a2), "r"(a3), "r"(b0), "r"(b1));
        }
    }

    int r1 = row0 + m0 + gq;
    int r2 = r1 + 8;
    float d1 = (r1 < n) ? g_dis[r1] : 0.f;
    float d2 = (r2 < n) ? g_dis[r2] : 0.f;
#pragma unroll
    for (int nt = 0; nt < 8; nt++) {
        int col = n0 + nt * 8 + tq * 2;
        if (r1 < n) *(__half2*)&C[(size_t)r1 * F + col] = __floats2half2_rn(acc[nt][0] * d1, acc[nt][1] * d1);
        if (r2 < n) *(__half2*)&C[(size_t)r2 * F + col] = __floats2half2_rn(acc[nt][2] * d2, acc[nt][3] * d2);
    }
}

// ---------------- CSR gather (warp/node, depth-3 fp16 tree, aligned) -------
__device__ __forceinline__ void acc2(float4& s, uint2 u) {
    float2 a = __half22float2(*(const __half2*)&u.x);
    float2 b = __half22float2(*(const __half2*)&u.y);
    s.x += a.x; s.y += a.y; s.z += b.x; s.w += b.y;
}

// depth-2 fp16 tree over 4 gathered rows (remainder path)
__device__ __forceinline__ void accq(float4& s, uint2 u0, uint2 u1, uint2 u2, uint2 u3) {
    __half2 ax = __hadd2(*(const __half2*)&u0.x, *(const __half2*)&u1.x);
    __half2 ay = __hadd2(*(const __half2*)&u0.y, *(const __half2*)&u1.y);
    __half2 bx = __hadd2(*(const __half2*)&u2.x, *(const __half2*)&u3.x);
    __half2 by = __hadd2(*(const __half2*)&u2.y, *(const __half2*)&u3.y);
    __half2 qx = __hadd2(ax, bx);
    __half2 qy = __hadd2(ay, by);
    float2 fx = __half22float2(qx);
    float2 fy = __half22float2(qy);
    s.x += fx.x; s.y += fx.y; s.z += fy.x; s.w += fy.y;
}

// depth-3 fp16 tree over 8 gathered rows: 14 HADD2 + 4 CVT + 4 FADD
__device__ __forceinline__ void acco(float4& s,
                                     uint2 u0, uint2 u1, uint2 u2, uint2 u3,
                                     uint2 u4, uint2 u5, uint2 u6, uint2 u7) {
    __half2 p0x = __hadd2(*(const __half2*)&u0.x, *(const __half2*)&u1.x);
    __half2 p1x = __hadd2(*(const __half2*)&u2.x, *(const __half2*)&u3.x);
    __half2 p2x = __hadd2(*(const __half2*)&u4.x, *(const __half2*)&u5.x);
    __half2 p3x = __hadd2(*(const __half2*)&u6.x, *(const __half2*)&u7.x);
    __half2 p0y = __hadd2(*(const __half2*)&u0.y, *(const __half2*)&u1.y);
    __half2 p1y = __hadd2(*(const __half2*)&u2.y, *(const __half2*)&u3.y);
    __half2 p2y = __hadd2(*(const __half2*)&u4.y, *(const __half2*)&u5.y);
    __half2 p3y = __hadd2(*(const __half2*)&u6.y, *(const __half2*)&u7.y);
    __half2 q0x = __hadd2(p0x, p1x);
    __half2 q1x = __hadd2(p2x, p3x);
    __half2 q0y = __hadd2(p0y, p1y);
    __half2 q1y = __hadd2(p2y, p3y);
    __half2 rx = __hadd2(q0x, q1x);
    __half2 ry = __hadd2(q0y, q1y);
    float2 fx = __half22float2(rx);
    float2 fy = __half22float2(ry);
    s.x += fx.x; s.y += fx.y; s.z += fy.x; s.w += fy.y;
}

__device__ __forceinline__ float4 agg_row(const uint2* __restrict__ gp,
                                          int node, int lane) {
    float4 s = make_float4(0.f, 0.f, 0.f, 0.f);
    acc2(s, __ldg(&gp[(size_t)node * 32 + lane]));    // self loop (pre-scaled)
    int i = g_rowptr[node];
    int end = g_rowptr[node + 1];                     // padded: (end-i) % 4 == 0
    for (; i + 8 <= end; i += 8) {
        int4 ia = __ldg((const int4*)&g_csr[i]);
        int4 ib = __ldg((const int4*)&g_csr[i + 4]);
        uint2 u0 = __ldg(&gp[(size_t)ia.x * 32 + lane]);
        uint2 u1 = __ldg(&gp[(size_t)ia.y * 32 + lane]);
        uint2 u2 = __ldg(&gp[(size_t)ia.z * 32 + lane]);
        uint2 u3 = __ldg(&gp[(size_t)ia.w * 32 + lane]);
        uint2 u4 = __ldg(&gp[(size_t)ib.x * 32 + lane]);
        uint2 u5 = __ldg(&gp[(size_t)ib.y * 32 + lane]);
        uint2 u6 = __ldg(&gp[(size_t)ib.z * 32 + lane]);
        uint2 u7 = __ldg(&gp[(size_t)ib.w * 32 + lane]);
        acco(s, u0, u1, u2, u3, u4, u5, u6, u7);
    }
    if (i < end) {                                    // exactly one 4-block
        int4 ia = __ldg((const int4*)&g_csr[i]);
        uint2 u0 = __ldg(&gp[(size_t)ia.x * 32 + lane]);
        uint2 u1 = __ldg(&gp[(size_t)ia.y * 32 + lane]);
        uint2 u2 = __ldg(&gp[(size_t)ia.z * 32 + lane]);
        uint2 u3 = __ldg(&gp[(size_t)ia.w * 32 + lane]);
        accq(s, u0, u1, u2, u3);
    }
    return s;
}

// h1 = fp16(relu(dis*sum + b))
__global__ void __launch_bounds__(256) agg1_kernel(const float* __restrict__ b, int n) {
    int w = (blockIdx.x * blockDim.x + threadIdx.x) >> 5;
    int lane = threadIdx.x & 31;
    if (w >= n) return;
    float4 s = agg_row((const uint2*)g_t1, w, lane);
    float d = g_dis[w];
    float4 bb = __ldg((const float4*)&b[lane * 4]);
    float ox = fmaxf(fmaf(d, s.x, bb.x), 0.f);
    float oy = fmaxf(fmaf(d, s.y, bb.y), 0.f);
    float oz = fmaxf(fmaf(d, s.z, bb.z), 0.f);
    float ow = fmaxf(fmaf(d, s.w, bb.w), 0.f);
    __half2 p0 = __floats2half2_rn(ox, oy);
    __half2 p1 = __floats2half2_rn(oz, ow);
    uint2 st;
    st.x = *(uint32_t*)&p0;
    st.y = *(uint32_t*)&p1;
    ((uint2*)g_h1)[(size_t)w * 32 + lane] = st;
}

// o = relu(dis*sum + b) * inv_count; mean-pool scatter
__global__ void __launch_bounds__(256) agg2_kernel(
    const void* __restrict__ batch, const float* __restrict__ b,
    float* __restrict__ out, int n)
{
    int w = (blockIdx.x * blockDim.x + threadIdx.x) >> 5;
    int lane = threadIdx.x & 31;
    if (w >= n) return;
    float4 s = agg_row((const uint2*)g_t2, w, lane);
    float d = g_dis[w];
    float4 bb = __ldg((const float4*)&b[lane * 4]);
    long long gid = load_idx(batch, w, g_b64);
    float inv = __ldg(&g_inv[gid]);
    float ox = fmaxf(fmaf(d, s.x, bb.x), 0.f) * inv;
    float oy = fmaxf(fmaf(d, s.y, bb.y), 0.f) * inv;
    float oz = fmaxf(fmaf(d, s.z, bb.z), 0.f) * inv;
    float ow = fmaxf(fmaf(d, s.w, bb.w), 0.f) * inv;
    float* p = &out[(size_t)gid * F + lane * 4];
    asm volatile("red.global.add.v4.f32 [%0], {%1,%2,%3,%4};"
                 :: "l"(p), "f"(ox), "f"(oy), "f"(oz), "f"(ow) : "memory");
}

// ---------------- launch ----------------
extern "C" void kernel_launch(void* const* d_in, const int* in_sizes, int n_in,
                              void* d_out, int out_size) {
    const float* x    = (const float*)d_in[0];
    const void*  edge = d_in[1];
    const void*  batch= d_in[2];
    const float* W1   = (const float*)d_in[3];
    const float* b1   = (const float*)d_in[4];
    const float* W2   = (const float*)d_in[5];
    const float* b2   = (const float*)d_in[6];
    float* out = (float*)d_out;

    int N = in_sizes[0] / F;
    int E = in_sizes[1] / 2;
    int G = out_size / F;

    void *p_t1, *p_h1, *p_t2, *p_w1t, *p_w2t;
    cudaGetSymbolAddress(&p_t1, g_t1);
    cudaGetSymbolAddress(&p_h1, g_h1);
    cudaGetSymbolAddress(&p_t2, g_t2);
    cudaGetSymbolAddress(&p_w1t, g_w1t);
    cudaGetSymbolAddress(&p_w2t, g_w2t);

    const int SMEM = 2 * 128 * SA * (int)sizeof(__half);   // 69632 bytes
    cudaFuncSetAttribute(gemm_mma_kernel<false>, cudaFuncAttributeMaxDynamicSharedMemorySize, SMEM);
    cudaFuncSetAttribute(gemm_mma_kernel<true>,  cudaFuncAttributeMaxDynamicSharedMemorySize, SMEM);

    const int TB = 256;
    int gemm_grid = (N + 127) / 128;
    int agg_grid = (N + 7) / 8;

    // launches: 0 prep1, 1 prep2, 2 gemm1, 3 agg1 (profiled), 4 gemm2, 5 agg2
    prep1_kernel<<<PREP_BLOCKS, PREP_THREADS>>>(edge, batch, W1, W2, out, G * F, N, E);
    prep2_kernel<<<PREP_BLOCKS, PREP_THREADS>>>(edge, N, E, N);
    gemm_mma_kernel<false><<<gemm_grid, 512, SMEM>>>(x, (const __half*)p_w1t, (__half*)p_t1, N);
    agg1_kernel<<<agg_grid, TB>>>(b1, N);
    gemm_mma_kernel<true><<<gemm_grid, 512, SMEM>>>(p_h1, (const __half*)p_w2t, (__half*)p_t2, N);
    agg2_kernel<<<agg_grid, TB>>>(batch, b2, out, N);
}